// round 4
// baseline (speedup 1.0000x reference)
#include <cuda_runtime.h>
#include <math.h>

// ---------------------------------------------------------------------------
// Problem constants
// ---------------------------------------------------------------------------
#define T_DIM   1024
#define B_DIM   4
#define D_DIM   768
#define H_DIM   12
#define HD_DIM  64
#define FF_DIM  3072
#define NROWS   4096          // T*B
#define NHEADS  48            // B*H
#define ALPHA_C 2.2133638394006434f   // 24^0.25
#define QSCALE  0.00390625f           // 0.125/32

// ---------------------------------------------------------------------------
// Scratch (device globals: allocation-free rule)
// ---------------------------------------------------------------------------
__device__ float g_q   [NHEADS * T_DIM * HD_DIM];   // head-major, scaled q
__device__ float g_k   [NHEADS * T_DIM * HD_DIM];
__device__ float g_v   [NHEADS * T_DIM * HD_DIM];
__device__ float g_gate[NHEADS * T_DIM];
__device__ float g_ctx [NROWS * D_DIM];             // attention context (T,B,D)
__device__ float g_y1  [NROWS * D_DIM];             // states*ALPHA + attn_out
__device__ float g_x   [NROWS * D_DIM];             // LN1 output
__device__ float g_h   [NROWS * FF_DIM];            // gelu(x@W1^T+b1)
__device__ float g_y2  [NROWS * D_DIM];             // h@W2^T+b2 + x*ALPHA

// ---------------------------------------------------------------------------
// Generic tiled SGEMM:  C = A(N x K) @ W(M x K)^T  (+ epilogue)
// 128x128 block tile, BK=16, 256 threads, 8x8 per-thread microtile.
// ---------------------------------------------------------------------------
enum { EPI_SCATTER_SCALE = 0, EPI_SCATTER = 1, EPI_ADD_ALPHA = 2, EPI_GELU = 3 };

template <int EPI>
__global__ __launch_bounds__(256, 2) void sgemm_nt(
    const float* __restrict__ A, const float* __restrict__ W,
    const float* __restrict__ bias, const float* __restrict__ aux,
    float* __restrict__ C, int K)
{
    __shared__ float As[16][132];   // [k][row], pad 4 keeps float4 alignment
    __shared__ float Bs[16][132];   // [k][col]

    const int n0  = blockIdx.y * 128;
    const int m0  = blockIdx.x * 128;
    const int tid = threadIdx.x;
    const int tx  = tid & 15;
    const int ty  = tid >> 4;

    float acc[8][8];
#pragma unroll
    for (int i = 0; i < 8; i++)
#pragma unroll
        for (int j = 0; j < 8; j++) acc[i][j] = 0.f;

    const float* Ab = A + (size_t)n0 * K;
    const float* Wb = W + (size_t)m0 * K;

    for (int kt = 0; kt < K; kt += 16) {
        // 2048 floats per operand = 512 float4; 2 per thread
#pragma unroll
        for (int u = 0; u < 2; u++) {
            int f4  = tid + u * 256;
            int row = f4 >> 2;
            int kq  = (f4 & 3) * 4;
            float4 av = *(const float4*)(Ab + (size_t)row * K + kt + kq);
            As[kq + 0][row] = av.x; As[kq + 1][row] = av.y;
            As[kq + 2][row] = av.z; As[kq + 3][row] = av.w;
            float4 bv = *(const float4*)(Wb + (size_t)row * K + kt + kq);
            Bs[kq + 0][row] = bv.x; Bs[kq + 1][row] = bv.y;
            Bs[kq + 2][row] = bv.z; Bs[kq + 3][row] = bv.w;
        }
        __syncthreads();

#pragma unroll
        for (int k = 0; k < 16; k++) {
            float a[8], b[8];
            *(float4*)(a)     = *(const float4*)&As[k][ty * 8];
            *(float4*)(a + 4) = *(const float4*)&As[k][ty * 8 + 4];
            *(float4*)(b)     = *(const float4*)&Bs[k][tx * 8];
            *(float4*)(b + 4) = *(const float4*)&Bs[k][tx * 8 + 4];
#pragma unroll
            for (int i = 0; i < 8; i++)
#pragma unroll
                for (int j = 0; j < 8; j++)
                    acc[i][j] += a[i] * b[j];
        }
        __syncthreads();
    }

    // Epilogue
#pragma unroll
    for (int i = 0; i < 8; i++) {
        const int n = n0 + ty * 8 + i;
#pragma unroll
        for (int j = 0; j < 8; j++) {
            const int m = m0 + tx * 8 + j;
            float v = acc[i][j] + bias[m];
            if (EPI == EPI_SCATTER_SCALE || EPI == EPI_SCATTER) {
                if (EPI == EPI_SCATTER_SCALE) v *= QSCALE;
                // states rows: n = t*4 + b ; cols: m = h*64 + hd
                const int t = n >> 2, b = n & 3, h = m >> 6, hd = m & 63;
                C[(((size_t)(b * H_DIM + h) * T_DIM) + t) * HD_DIM + hd] = v;
            } else if (EPI == EPI_ADD_ALPHA) {
                C[(size_t)n * D_DIM + m] = v + aux[(size_t)n * D_DIM + m] * ALPHA_C;
            } else { // EPI_GELU (exact)
                C[(size_t)n * FF_DIM + m] =
                    0.5f * v * (1.f + erff(v * 0.70710678118654752f));
            }
        }
    }
}

// ---------------------------------------------------------------------------
// Gate kernel: ga=sigmoid(q_full . sum(grep_w[0:4]) + sum(grep_b[0:4])), etc.
// One warp per (bh, t) row; q_full = g_q * 256.
// ---------------------------------------------------------------------------
__global__ void gate_kernel(const float* __restrict__ q,
                            const float* __restrict__ grep_w,
                            const float* __restrict__ grep_b,
                            const float* __restrict__ grep_a,
                            float* __restrict__ gate)
{
    const int idx  = blockIdx.x * 8 + (threadIdx.x >> 5);   // 0..49151
    const int lane = threadIdx.x & 31;
    const int d0 = lane, d1 = lane + 32;

    float wa0 = grep_w[d0] + grep_w[64 + d0] + grep_w[128 + d0] + grep_w[192 + d0];
    float wa1 = grep_w[d1] + grep_w[64 + d1] + grep_w[128 + d1] + grep_w[192 + d1];
    float wb0 = grep_w[256 + d0] + grep_w[320 + d0] + grep_w[384 + d0] + grep_w[448 + d0];
    float wb1 = grep_w[256 + d1] + grep_w[320 + d1] + grep_w[384 + d1] + grep_w[448 + d1];

    const float* qr = q + (size_t)idx * 64;
    float q0 = qr[d0] * 256.f, q1 = qr[d1] * 256.f;
    float sa = q0 * wa0 + q1 * wa1;
    float sb = q0 * wb0 + q1 * wb1;
#pragma unroll
    for (int o = 16; o; o >>= 1) {
        sa += __shfl_xor_sync(0xffffffffu, sa, o);
        sb += __shfl_xor_sync(0xffffffffu, sb, o);
    }
    if (lane == 0) {
        sa += grep_b[0] + grep_b[1] + grep_b[2] + grep_b[3];
        sb += grep_b[4] + grep_b[5] + grep_b[6] + grep_b[7];
        float ga = 1.f / (1.f + __expf(-sa));
        float gb = 1.f / (1.f + __expf(-sb));
        int h = (idx >> 10) % H_DIM;
        gate[idx] = ga * (gb * grep_a[h] - 1.f) + 2.f;
    }
}

// ---------------------------------------------------------------------------
// Flash attention (fp32): logits = 32*(q.k) + gate*pb ; online softmax.
// Grid (T/64, 48). 256 threads = 8 warps; each warp owns 8 q-rows.
// ---------------------------------------------------------------------------
__global__ __launch_bounds__(256) void flash_attn(
    const float* __restrict__ q, const float* __restrict__ k,
    const float* __restrict__ v, const float* __restrict__ pb,
    const float* __restrict__ gate, float* __restrict__ ctx)
{
    extern __shared__ float sm[];
    float* Qs = sm;             // 64x64
    float* Kt = Qs + 4096;      // [d][col] stride 65 (conflict-free)
    float* Vs = Kt + 4160;      // [col][d]
    float* Ps = Vs + 4096;      // [row][col]
    float* Gs = Ps + 4096;      // 64 gates

    const int bh   = blockIdx.y;
    const int q0   = blockIdx.x * 64;
    const int tid  = threadIdx.x;
    const int lane = tid & 31;
    const int w    = tid >> 5;

    const float* qb = q + ((size_t)bh * T_DIM + q0) * 64;
    for (int i = tid; i < 1024; i += 256)
        ((float4*)Qs)[i] = ((const float4*)qb)[i];
    if (tid < 64) Gs[tid] = gate[bh * T_DIM + q0 + tid];

    float m[8], l[8], a0[8], a1[8];
#pragma unroll
    for (int r = 0; r < 8; r++) { m[r] = -1e30f; l[r] = 0.f; a0[r] = 0.f; a1[r] = 0.f; }

    const float* kb  = k + (size_t)bh * 65536;
    const float* vb  = v + (size_t)bh * 65536;
    const float* pbb = pb + (size_t)bh * 1048576 + (size_t)(q0 + w * 8) * 1024;
    const float* Qw  = Qs + w * 8 * 64;

    for (int ktile = 0; ktile < 16; ktile++) {
        // load K transposed (scalar, conflict-free), V straight (float4)
        const float* kg = kb + ktile * 4096;
#pragma unroll
        for (int it = 0; it < 16; it++) {
            int idx = it * 256 + tid;
            Kt[(idx & 63) * 65 + (idx >> 6)] = kg[idx];
        }
        const float4* vg = (const float4*)(vb + ktile * 4096);
        for (int i = tid; i < 1024; i += 256)
            ((float4*)Vs)[i] = vg[i];
        __syncthreads();

        // S = Q @ K^T for this warp's 8 rows; lane holds cols {lane, lane+32}
        float s0[8], s1[8];
#pragma unroll
        for (int r = 0; r < 8; r++) { s0[r] = 0.f; s1[r] = 0.f; }
#pragma unroll 8
        for (int d = 0; d < 64; d++) {
            float k0 = Kt[d * 65 + lane];
            float k1 = Kt[d * 65 + 32 + lane];
#pragma unroll
            for (int r = 0; r < 8; r++) {
                float qv = Qw[r * 64 + d];
                s0[r] += qv * k0;
                s1[r] += qv * k1;
            }
        }

        // logits + online softmax
        const float* pbt = pbb + ktile * 64;
#pragma unroll
        for (int r = 0; r < 8; r++) {
            float g  = Gs[w * 8 + r];
            float l0 = 32.f * s0[r] + g * pbt[(size_t)r * 1024 + lane];
            float l1 = 32.f * s1[r] + g * pbt[(size_t)r * 1024 + 32 + lane];
            float mx = fmaxf(l0, l1);
#pragma unroll
            for (int o = 16; o; o >>= 1)
                mx = fmaxf(mx, __shfl_xor_sync(0xffffffffu, mx, o));
            float mn   = fmaxf(m[r], mx);
            float p0   = __expf(l0 - mn);
            float p1   = __expf(l1 - mn);
            float corr = __expf(m[r] - mn);
            m[r] = mn;
            float ps = p0 + p1;
#pragma unroll
            for (int o = 16; o; o >>= 1)
                ps += __shfl_xor_sync(0xffffffffu, ps, o);
            l[r]  = l[r] * corr + ps;
            a0[r] *= corr;
            a1[r] *= corr;
            Ps[(w * 8 + r) * 64 + lane]      = p0;
            Ps[(w * 8 + r) * 64 + 32 + lane] = p1;
        }
        __syncwarp();

        // acc += P @ V ; lane holds dims {lane, lane+32}
        const float* Pw = Ps + w * 8 * 64;
#pragma unroll 8
        for (int c = 0; c < 64; c++) {
            float v0 = Vs[c * 64 + lane];
            float v1 = Vs[c * 64 + 32 + lane];
#pragma unroll
            for (int r = 0; r < 8; r++) {
                float p = Pw[r * 64 + c];
                a0[r] += p * v0;
                a1[r] += p * v1;
            }
        }
        __syncthreads();
    }

    // write ctx back to (T,B,D) layout for Wo GEMM
    const int b = bh / H_DIM, hh = bh % H_DIM;
#pragma unroll
    for (int r = 0; r < 8; r++) {
        int   t   = q0 + w * 8 + r;
        float inv = 1.f / l[r];
        float* dst = ctx + ((size_t)(t * B_DIM + b)) * D_DIM + hh * 64;
        dst[lane]      = a0[r] * inv;
        dst[32 + lane] = a1[r] * inv;
    }
}

// ---------------------------------------------------------------------------
// LayerNorm: one block per row of 768.
// ---------------------------------------------------------------------------
__global__ void layernorm_kernel(const float* __restrict__ in,
                                 const float* __restrict__ g,
                                 const float* __restrict__ b,
                                 float* __restrict__ out)
{
    const int row = blockIdx.x, tid = threadIdx.x;
    const float* xr = in + (size_t)row * D_DIM;
    float v0 = xr[tid], v1 = xr[tid + 256], v2 = xr[tid + 512];
    float s  = v0 + v1 + v2;
    float sq = v0 * v0 + v1 * v1 + v2 * v2;
#pragma unroll
    for (int o = 16; o; o >>= 1) {
        s  += __shfl_xor_sync(0xffffffffu, s,  o);
        sq += __shfl_xor_sync(0xffffffffu, sq, o);
    }
    __shared__ float ss[8], sqs[8], stats[2];
    const int w = tid >> 5, lane = tid & 31;
    if (lane == 0) { ss[w] = s; sqs[w] = sq; }
    __syncthreads();
    if (tid == 0) {
        float S = 0.f, SQ = 0.f;
        for (int i = 0; i < 8; i++) { S += ss[i]; SQ += sqs[i]; }
        float mu  = S * (1.f / 768.f);
        float var = SQ * (1.f / 768.f) - mu * mu;
        stats[0] = mu;
        stats[1] = rsqrtf(var + 1e-5f);
    }
    __syncthreads();
    const float mu = stats[0], rstd = stats[1];
    float* orow = out + (size_t)row * D_DIM;
    orow[tid]       = (v0 - mu) * rstd * g[tid]       + b[tid];
    orow[tid + 256] = (v1 - mu) * rstd * g[tid + 256] + b[tid + 256];
    orow[tid + 512] = (v2 - mu) * rstd * g[tid + 512] + b[tid + 512];
}

// ---------------------------------------------------------------------------
// Launch
// ---------------------------------------------------------------------------
extern "C" void kernel_launch(void* const* d_in, const int* in_sizes, int n_in,
                              void* d_out, int out_size)
{
    const float* states = (const float*)d_in[0];
    const float* pb     = (const float*)d_in[1];
    const float* Wq = (const float*)d_in[2];   const float* bq = (const float*)d_in[3];
    const float* Wk = (const float*)d_in[4];   const float* bk = (const float*)d_in[5];
    const float* Wv = (const float*)d_in[6];   const float* bv = (const float*)d_in[7];
    const float* Wo = (const float*)d_in[8];   const float* bo = (const float*)d_in[9];
    const float* grep_w = (const float*)d_in[10];
    const float* grep_b = (const float*)d_in[11];
    const float* grep_a = (const float*)d_in[12];
    const float* ln1_g  = (const float*)d_in[13];
    const float* ln1_b  = (const float*)d_in[14];
    const float* W1 = (const float*)d_in[15];  const float* b1 = (const float*)d_in[16];
    const float* W2 = (const float*)d_in[17];  const float* b2 = (const float*)d_in[18];
    const float* ln2_g  = (const float*)d_in[19];
    const float* ln2_b  = (const float*)d_in[20];
    float* out = (float*)d_out;

    float *q, *k, *v, *gate, *ctx, *y1, *x, *h, *y2;
    cudaGetSymbolAddress((void**)&q,    g_q);
    cudaGetSymbolAddress((void**)&k,    g_k);
    cudaGetSymbolAddress((void**)&v,    g_v);
    cudaGetSymbolAddress((void**)&gate, g_gate);
    cudaGetSymbolAddress((void**)&ctx,  g_ctx);
    cudaGetSymbolAddress((void**)&y1,   g_y1);
    cudaGetSymbolAddress((void**)&x,    g_x);
    cudaGetSymbolAddress((void**)&h,    g_h);
    cudaGetSymbolAddress((void**)&y2,   g_y2);

    const dim3 blk(256);

    // QKV projections (scattered to head-major)
    sgemm_nt<EPI_SCATTER_SCALE><<<dim3(6, 32), blk>>>(states, Wq, bq, nullptr, q, D_DIM);
    sgemm_nt<EPI_SCATTER>      <<<dim3(6, 32), blk>>>(states, Wk, bk, nullptr, k, D_DIM);
    sgemm_nt<EPI_SCATTER>      <<<dim3(6, 32), blk>>>(states, Wv, bv, nullptr, v, D_DIM);

    // gating
    gate_kernel<<<NHEADS * T_DIM / 8, blk>>>(q, grep_w, grep_b, grep_a, gate);

    // fused attention
    cudaFuncSetAttribute(flash_attn, cudaFuncAttributeMaxDynamicSharedMemorySize, 66048);
    flash_attn<<<dim3(T_DIM / 64, NHEADS), blk, 66048>>>(q, k, v, pb, gate, ctx);

    // Wo projection + residual (states*ALPHA), then LN1
    sgemm_nt<EPI_ADD_ALPHA><<<dim3(6, 32), blk>>>(ctx, Wo, bo, states, y1, D_DIM);
    layernorm_kernel<<<NROWS, blk>>>(y1, ln1_g, ln1_b, x);

    // FFN
    sgemm_nt<EPI_GELU>     <<<dim3(24, 32), blk>>>(x, W1, b1, nullptr, h, D_DIM);
    sgemm_nt<EPI_ADD_ALPHA><<<dim3(6, 32),  blk>>>(h, W2, b2, x, y2, FF_DIM);
    layernorm_kernel<<<NROWS, blk>>>(y2, ln2_g, ln2_b, out);

    // second output: passthrough positional_bias
    cudaMemcpyAsync(out + (size_t)NROWS * D_DIM, pb,
                    (size_t)NHEADS * T_DIM * T_DIM * sizeof(float),
                    cudaMemcpyDeviceToDevice, 0);
}

// round 5
// speedup vs baseline: 1.1218x; 1.1218x over previous
#include <cuda_runtime.h>
#include <math.h>

// ---------------------------------------------------------------------------
// Problem constants
// ---------------------------------------------------------------------------
#define T_DIM   1024
#define B_DIM   4
#define D_DIM   768
#define H_DIM   12
#define HD_DIM  64
#define FF_DIM  3072
#define NROWS   4096          // T*B
#define NHEADS  48            // B*H
#define ALPHA_C 2.2133638394006434f   // 24^0.25
#define QSCALE  0.00390625f           // 0.125/32

// ---------------------------------------------------------------------------
// Scratch (device globals: allocation-free rule)
// ---------------------------------------------------------------------------
__device__ float g_q   [NHEADS * T_DIM * HD_DIM];
__device__ float g_k   [NHEADS * T_DIM * HD_DIM];
__device__ float g_v   [NHEADS * T_DIM * HD_DIM];
__device__ float g_gate[NHEADS * T_DIM];
__device__ float g_ctx [NROWS * D_DIM];
__device__ float g_y1  [NROWS * D_DIM];
__device__ float g_x   [NROWS * D_DIM];
__device__ float g_h   [NROWS * FF_DIM];
__device__ float g_y2  [NROWS * D_DIM];

// ---------------------------------------------------------------------------
// tf32 mma helpers
// ---------------------------------------------------------------------------
__device__ __forceinline__ unsigned f2tf32(float x) {
    unsigned y;
    asm("cvt.rna.tf32.f32 %0, %1;" : "=r"(y) : "f"(x));
    return y;
}

__device__ __forceinline__ void mma_tf32(float* d, const unsigned* a, const unsigned* b) {
    asm volatile(
        "mma.sync.aligned.m16n8k8.row.col.f32.tf32.tf32.f32 "
        "{%0,%1,%2,%3}, {%4,%5,%6,%7}, {%8,%9}, {%0,%1,%2,%3};\n"
        : "+f"(d[0]), "+f"(d[1]), "+f"(d[2]), "+f"(d[3])
        : "r"(a[0]), "r"(a[1]), "r"(a[2]), "r"(a[3]),
          "r"(b[0]), "r"(b[1]));
}

// ---------------------------------------------------------------------------
// tf32 tensor-core GEMM:  C = A(N x K) @ W(M x K)^T  (+ fused epilogue)
// 128x128 tile, BK=16, 256 threads (8 warps as 4x2), warp tile 32x64.
// E_QKV: one launch computes Q,K,V (blockIdx.x/6 selects weight), scattering
// to head-major layout (Q additionally scaled by QSCALE).
// ---------------------------------------------------------------------------
enum { E_QKV = 0, E_ADD_ALPHA = 1, E_GELU = 2 };

template <int EPI>
__global__ __launch_bounds__(256, 2) void mm_tf32(
    const float* __restrict__ A,
    const float* __restrict__ W0, const float* __restrict__ W1, const float* __restrict__ W2,
    const float* __restrict__ bp0, const float* __restrict__ bp1, const float* __restrict__ bp2,
    const float* __restrict__ aux,
    float* __restrict__ C0, float* __restrict__ C1, float* __restrict__ C2,
    int K, int ldc)
{
    __shared__ unsigned As[16 * 132];   // [k][row], stride 132 (<=2-way conflicts)
    __shared__ unsigned Bs[16 * 132];   // [k][col]

    int sel = 0, mblk = blockIdx.x;
    const float* W = W0; const float* bias = bp0; float* C = C0;
    if (EPI == E_QKV) {
        sel  = blockIdx.x / 6;
        mblk = blockIdx.x % 6;
        if (sel == 1) { W = W1; bias = bp1; C = C1; }
        else if (sel == 2) { W = W2; bias = bp2; C = C2; }
    }

    const int n0 = blockIdx.y * 128;   // A-row block
    const int m0 = mblk * 128;         // W-row (output col) block
    const int tid  = threadIdx.x;
    const int lane = tid & 31;
    const int wid  = tid >> 5;
    const int wr = (wid >> 1) * 32;    // warp row offset in tile
    const int wc = (wid & 1)  * 64;    // warp col offset in tile
    const int g = lane >> 2;           // groupID
    const int c = lane & 3;            // threadID-in-group

    float acc[2][8][4];
#pragma unroll
    for (int mf = 0; mf < 2; mf++)
#pragma unroll
        for (int nf = 0; nf < 8; nf++)
#pragma unroll
            for (int r = 0; r < 4; r++) acc[mf][nf][r] = 0.f;

    const float* Ab = A + (size_t)n0 * K;
    const float* Wb = W + (size_t)m0 * K;

    const int row_ld = tid >> 2;        // 0..63 (second chunk: +64)
    const int kq     = (tid & 3) * 4;

    float4 pa0, pa1, pb0, pb1;
    // prefetch first tile
    {
        pa0 = *(const float4*)(Ab + (size_t)row_ld * K + kq);
        pa1 = *(const float4*)(Ab + (size_t)(row_ld + 64) * K + kq);
        pb0 = *(const float4*)(Wb + (size_t)row_ld * K + kq);
        pb1 = *(const float4*)(Wb + (size_t)(row_ld + 64) * K + kq);
    }

    for (int kt = 0; kt < K; kt += 16) {
        // store staged tile (convert to tf32)
        As[(kq + 0) * 132 + row_ld] = f2tf32(pa0.x);
        As[(kq + 1) * 132 + row_ld] = f2tf32(pa0.y);
        As[(kq + 2) * 132 + row_ld] = f2tf32(pa0.z);
        As[(kq + 3) * 132 + row_ld] = f2tf32(pa0.w);
        As[(kq + 0) * 132 + row_ld + 64] = f2tf32(pa1.x);
        As[(kq + 1) * 132 + row_ld + 64] = f2tf32(pa1.y);
        As[(kq + 2) * 132 + row_ld + 64] = f2tf32(pa1.z);
        As[(kq + 3) * 132 + row_ld + 64] = f2tf32(pa1.w);
        Bs[(kq + 0) * 132 + row_ld] = f2tf32(pb0.x);
        Bs[(kq + 1) * 132 + row_ld] = f2tf32(pb0.y);
        Bs[(kq + 2) * 132 + row_ld] = f2tf32(pb0.z);
        Bs[(kq + 3) * 132 + row_ld] = f2tf32(pb0.w);
        Bs[(kq + 0) * 132 + row_ld + 64] = f2tf32(pb1.x);
        Bs[(kq + 1) * 132 + row_ld + 64] = f2tf32(pb1.y);
        Bs[(kq + 2) * 132 + row_ld + 64] = f2tf32(pb1.z);
        Bs[(kq + 3) * 132 + row_ld + 64] = f2tf32(pb1.w);
        __syncthreads();

        // prefetch next tile (overlaps with MMA below)
        if (kt + 16 < K) {
            const int k2 = kt + 16;
            pa0 = *(const float4*)(Ab + (size_t)row_ld * K + k2 + kq);
            pa1 = *(const float4*)(Ab + (size_t)(row_ld + 64) * K + k2 + kq);
            pb0 = *(const float4*)(Wb + (size_t)row_ld * K + k2 + kq);
            pb1 = *(const float4*)(Wb + (size_t)(row_ld + 64) * K + k2 + kq);
        }

#pragma unroll
        for (int ks = 0; ks < 2; ks++) {
            const int kb = ks * 8;
            unsigned af[2][4], bf[8][2];
#pragma unroll
            for (int mf = 0; mf < 2; mf++) {
                const int r = wr + mf * 16 + g;
                af[mf][0] = As[(kb + c) * 132 + r];
                af[mf][1] = As[(kb + c) * 132 + r + 8];
                af[mf][2] = As[(kb + c + 4) * 132 + r];
                af[mf][3] = As[(kb + c + 4) * 132 + r + 8];
            }
#pragma unroll
            for (int nf = 0; nf < 8; nf++) {
                const int col = wc + nf * 8 + g;
                bf[nf][0] = Bs[(kb + c) * 132 + col];
                bf[nf][1] = Bs[(kb + c + 4) * 132 + col];
            }
#pragma unroll
            for (int mf = 0; mf < 2; mf++)
#pragma unroll
                for (int nf = 0; nf < 8; nf++)
                    mma_tf32(acc[mf][nf], af[mf], bf[nf]);
        }
        __syncthreads();
    }

    // Epilogue
#pragma unroll
    for (int mf = 0; mf < 2; mf++) {
#pragma unroll
        for (int r2 = 0; r2 < 2; r2++) {
            const int n = n0 + wr + mf * 16 + g + r2 * 8;
#pragma unroll
            for (int nf = 0; nf < 8; nf++) {
#pragma unroll
                for (int j = 0; j < 2; j++) {
                    const int m = m0 + wc + nf * 8 + c * 2 + j;
                    float v = acc[mf][nf][r2 * 2 + j] + bias[m];
                    if (EPI == E_QKV) {
                        if (sel == 0) v *= QSCALE;
                        const int t = n >> 2, b = n & 3, h = m >> 6, hd = m & 63;
                        C[(((size_t)(b * H_DIM + h) * T_DIM) + t) * HD_DIM + hd] = v;
                    } else if (EPI == E_ADD_ALPHA) {
                        C[(size_t)n * ldc + m] = v + aux[(size_t)n * ldc + m] * ALPHA_C;
                    } else { // E_GELU (exact)
                        C[(size_t)n * ldc + m] =
                            0.5f * v * (1.f + erff(v * 0.70710678118654752f));
                    }
                }
            }
        }
    }
}

// ---------------------------------------------------------------------------
// Gate kernel
// ---------------------------------------------------------------------------
__global__ void gate_kernel(const float* __restrict__ q,
                            const float* __restrict__ grep_w,
                            const float* __restrict__ grep_b,
                            const float* __restrict__ grep_a,
                            float* __restrict__ gate)
{
    const int idx  = blockIdx.x * 8 + (threadIdx.x >> 5);
    const int lane = threadIdx.x & 31;
    const int d0 = lane, d1 = lane + 32;

    float wa0 = grep_w[d0] + grep_w[64 + d0] + grep_w[128 + d0] + grep_w[192 + d0];
    float wa1 = grep_w[d1] + grep_w[64 + d1] + grep_w[128 + d1] + grep_w[192 + d1];
    float wb0 = grep_w[256 + d0] + grep_w[320 + d0] + grep_w[384 + d0] + grep_w[448 + d0];
    float wb1 = grep_w[256 + d1] + grep_w[320 + d1] + grep_w[384 + d1] + grep_w[448 + d1];

    const float* qr = q + (size_t)idx * 64;
    float q0 = qr[d0] * 256.f, q1 = qr[d1] * 256.f;
    float sa = q0 * wa0 + q1 * wa1;
    float sb = q0 * wb0 + q1 * wb1;
#pragma unroll
    for (int o = 16; o; o >>= 1) {
        sa += __shfl_xor_sync(0xffffffffu, sa, o);
        sb += __shfl_xor_sync(0xffffffffu, sb, o);
    }
    if (lane == 0) {
        sa += grep_b[0] + grep_b[1] + grep_b[2] + grep_b[3];
        sb += grep_b[4] + grep_b[5] + grep_b[6] + grep_b[7];
        float ga = 1.f / (1.f + __expf(-sa));
        float gb = 1.f / (1.f + __expf(-sb));
        int h = (idx >> 10) % H_DIM;
        gate[idx] = ga * (gb * grep_a[h] - 1.f) + 2.f;
    }
}

// ---------------------------------------------------------------------------
// Flash attention (fp32): logits = 32*(q.k) + gate*pb ; online softmax.
// ---------------------------------------------------------------------------
__global__ __launch_bounds__(256) void flash_attn(
    const float* __restrict__ q, const float* __restrict__ k,
    const float* __restrict__ v, const float* __restrict__ pb,
    const float* __restrict__ gate, float* __restrict__ ctx)
{
    extern __shared__ float sm[];
    float* Qs = sm;
    float* Kt = Qs + 4096;
    float* Vs = Kt + 4160;
    float* Ps = Vs + 4096;
    float* Gs = Ps + 4096;

    const int bh   = blockIdx.y;
    const int q0   = blockIdx.x * 64;
    const int tid  = threadIdx.x;
    const int lane = tid & 31;
    const int w    = tid >> 5;

    const float* qb = q + ((size_t)bh * T_DIM + q0) * 64;
    for (int i = tid; i < 1024; i += 256)
        ((float4*)Qs)[i] = ((const float4*)qb)[i];
    if (tid < 64) Gs[tid] = gate[bh * T_DIM + q0 + tid];

    float m[8], l[8], a0[8], a1[8];
#pragma unroll
    for (int r = 0; r < 8; r++) { m[r] = -1e30f; l[r] = 0.f; a0[r] = 0.f; a1[r] = 0.f; }

    const float* kb  = k + (size_t)bh * 65536;
    const float* vb  = v + (size_t)bh * 65536;
    const float* pbb = pb + (size_t)bh * 1048576 + (size_t)(q0 + w * 8) * 1024;
    const float* Qw  = Qs + w * 8 * 64;

    for (int ktile = 0; ktile < 16; ktile++) {
        const float* kg = kb + ktile * 4096;
#pragma unroll
        for (int it = 0; it < 16; it++) {
            int idx = it * 256 + tid;
            Kt[(idx & 63) * 65 + (idx >> 6)] = kg[idx];
        }
        const float4* vg = (const float4*)(vb + ktile * 4096);
        for (int i = tid; i < 1024; i += 256)
            ((float4*)Vs)[i] = vg[i];
        __syncthreads();

        float s0[8], s1[8];
#pragma unroll
        for (int r = 0; r < 8; r++) { s0[r] = 0.f; s1[r] = 0.f; }
#pragma unroll 8
        for (int d = 0; d < 64; d++) {
            float k0 = Kt[d * 65 + lane];
            float k1 = Kt[d * 65 + 32 + lane];
#pragma unroll
            for (int r = 0; r < 8; r++) {
                float qv = Qw[r * 64 + d];
                s0[r] += qv * k0;
                s1[r] += qv * k1;
            }
        }

        const float* pbt = pbb + ktile * 64;
#pragma unroll
        for (int r = 0; r < 8; r++) {
            float g  = Gs[w * 8 + r];
            float l0 = 32.f * s0[r] + g * pbt[(size_t)r * 1024 + lane];
            float l1 = 32.f * s1[r] + g * pbt[(size_t)r * 1024 + 32 + lane];
            float mx = fmaxf(l0, l1);
#pragma unroll
            for (int o = 16; o; o >>= 1)
                mx = fmaxf(mx, __shfl_xor_sync(0xffffffffu, mx, o));
            float mn   = fmaxf(m[r], mx);
            float p0   = __expf(l0 - mn);
            float p1   = __expf(l1 - mn);
            float corr = __expf(m[r] - mn);
            m[r] = mn;
            float ps = p0 + p1;
#pragma unroll
            for (int o = 16; o; o >>= 1)
                ps += __shfl_xor_sync(0xffffffffu, ps, o);
            l[r]  = l[r] * corr + ps;
            a0[r] *= corr;
            a1[r] *= corr;
            Ps[(w * 8 + r) * 64 + lane]      = p0;
            Ps[(w * 8 + r) * 64 + 32 + lane] = p1;
        }
        __syncwarp();

        const float* Pw = Ps + w * 8 * 64;
#pragma unroll 8
        for (int cc = 0; cc < 64; cc++) {
            float v0 = Vs[cc * 64 + lane];
            float v1 = Vs[cc * 64 + 32 + lane];
#pragma unroll
            for (int r = 0; r < 8; r++) {
                float p = Pw[r * 64 + cc];
                a0[r] += p * v0;
                a1[r] += p * v1;
            }
        }
        __syncthreads();
    }

    const int b = bh / H_DIM, hh = bh % H_DIM;
#pragma unroll
    for (int r = 0; r < 8; r++) {
        int   t   = q0 + w * 8 + r;
        float inv = 1.f / l[r];
        float* dst = ctx + ((size_t)(t * B_DIM + b)) * D_DIM + hh * 64;
        dst[lane]      = a0[r] * inv;
        dst[32 + lane] = a1[r] * inv;
    }
}

// ---------------------------------------------------------------------------
// LayerNorm
// ---------------------------------------------------------------------------
__global__ void layernorm_kernel(const float* __restrict__ in,
                                 const float* __restrict__ g,
                                 const float* __restrict__ b,
                                 float* __restrict__ out)
{
    const int row = blockIdx.x, tid = threadIdx.x;
    const float* xr = in + (size_t)row * D_DIM;
    float v0 = xr[tid], v1 = xr[tid + 256], v2 = xr[tid + 512];
    float s  = v0 + v1 + v2;
    float sq = v0 * v0 + v1 * v1 + v2 * v2;
#pragma unroll
    for (int o = 16; o; o >>= 1) {
        s  += __shfl_xor_sync(0xffffffffu, s,  o);
        sq += __shfl_xor_sync(0xffffffffu, sq, o);
    }
    __shared__ float ss[8], sqs[8], stats[2];
    const int w = tid >> 5, lane = tid & 31;
    if (lane == 0) { ss[w] = s; sqs[w] = sq; }
    __syncthreads();
    if (tid == 0) {
        float S = 0.f, SQ = 0.f;
        for (int i = 0; i < 8; i++) { S += ss[i]; SQ += sqs[i]; }
        float mu  = S * (1.f / 768.f);
        float var = SQ * (1.f / 768.f) - mu * mu;
        stats[0] = mu;
        stats[1] = rsqrtf(var + 1e-5f);
    }
    __syncthreads();
    const float mu = stats[0], rstd = stats[1];
    float* orow = out + (size_t)row * D_DIM;
    orow[tid]       = (v0 - mu) * rstd * g[tid]       + b[tid];
    orow[tid + 256] = (v1 - mu) * rstd * g[tid + 256] + b[tid + 256];
    orow[tid + 512] = (v2 - mu) * rstd * g[tid + 512] + b[tid + 512];
}

// ---------------------------------------------------------------------------
// Launch
// ---------------------------------------------------------------------------
extern "C" void kernel_launch(void* const* d_in, const int* in_sizes, int n_in,
                              void* d_out, int out_size)
{
    const float* states = (const float*)d_in[0];
    const float* pb     = (const float*)d_in[1];
    const float* Wq = (const float*)d_in[2];   const float* bq = (const float*)d_in[3];
    const float* Wk = (const float*)d_in[4];   const float* bk = (const float*)d_in[5];
    const float* Wv = (const float*)d_in[6];   const float* bv = (const float*)d_in[7];
    const float* Wo = (const float*)d_in[8];   const float* bo = (const float*)d_in[9];
    const float* grep_w = (const float*)d_in[10];
    const float* grep_b = (const float*)d_in[11];
    const float* grep_a = (const float*)d_in[12];
    const float* ln1_g  = (const float*)d_in[13];
    const float* ln1_b  = (const float*)d_in[14];
    const float* W1 = (const float*)d_in[15];  const float* b1 = (const float*)d_in[16];
    const float* W2 = (const float*)d_in[17];  const float* b2 = (const float*)d_in[18];
    const float* ln2_g  = (const float*)d_in[19];
    const float* ln2_b  = (const float*)d_in[20];
    float* out = (float*)d_out;

    float *q, *k, *v, *gate, *ctx, *y1, *x, *h, *y2;
    cudaGetSymbolAddress((void**)&q,    g_q);
    cudaGetSymbolAddress((void**)&k,    g_k);
    cudaGetSymbolAddress((void**)&v,    g_v);
    cudaGetSymbolAddress((void**)&gate, g_gate);
    cudaGetSymbolAddress((void**)&ctx,  g_ctx);
    cudaGetSymbolAddress((void**)&y1,   g_y1);
    cudaGetSymbolAddress((void**)&x,    g_x);
    cudaGetSymbolAddress((void**)&h,    g_h);
    cudaGetSymbolAddress((void**)&y2,   g_y2);

    const dim3 blk(256);

    // Fused QKV projections (tensor cores, scattered to head-major)
    mm_tf32<E_QKV><<<dim3(18, 32), blk>>>(states, Wq, Wk, Wv, bq, bk, bv,
                                          nullptr, q, k, v, D_DIM, 0);

    // gating
    gate_kernel<<<NHEADS * T_DIM / 8, blk>>>(q, grep_w, grep_b, grep_a, gate);

    // fused attention
    cudaFuncSetAttribute(flash_attn, cudaFuncAttributeMaxDynamicSharedMemorySize, 66048);
    flash_attn<<<dim3(T_DIM / 64, NHEADS), blk, 66048>>>(q, k, v, pb, gate, ctx);

    // Wo projection + residual, then LN1
    mm_tf32<E_ADD_ALPHA><<<dim3(6, 32), blk>>>(ctx, Wo, nullptr, nullptr, bo, nullptr, nullptr,
                                               states, y1, nullptr, nullptr, D_DIM, D_DIM);
    layernorm_kernel<<<NROWS, blk>>>(y1, ln1_g, ln1_b, x);

    // FFN
    mm_tf32<E_GELU><<<dim3(24, 32), blk>>>(x, W1, nullptr, nullptr, b1, nullptr, nullptr,
                                           nullptr, h, nullptr, nullptr, D_DIM, FF_DIM);
    mm_tf32<E_ADD_ALPHA><<<dim3(6, 32), blk>>>(h, W2, nullptr, nullptr, b2, nullptr, nullptr,
                                               x, y2, nullptr, nullptr, FF_DIM, D_DIM);
    layernorm_kernel<<<NROWS, blk>>>(y2, ln2_g, ln2_b, out);

    // second output: passthrough positional_bias
    cudaMemcpyAsync(out + (size_t)NROWS * D_DIM, pb,
                    (size_t)NHEADS * T_DIM * T_DIM * sizeof(float),
                    cudaMemcpyDeviceToDevice, 0);
}

// round 6
// speedup vs baseline: 2.2003x; 1.9615x over previous
#include <cuda_runtime.h>
#include <cuda_fp16.h>
#include <math.h>

// ---------------------------------------------------------------------------
// Problem constants
// ---------------------------------------------------------------------------
#define T_DIM   1024
#define B_DIM   4
#define D_DIM   768
#define H_DIM   12
#define HD_DIM  64
#define FF_DIM  3072
#define NROWS   4096          // T*B
#define NHEADS  48            // B*H
#define ALPHA_C 2.2133638394006434f   // 24^0.25
#define QSCALE  0.00390625f           // 0.125/32

// ---------------------------------------------------------------------------
// Scratch (device globals: allocation-free rule)
// ---------------------------------------------------------------------------
__device__ float g_q   [NHEADS * T_DIM * HD_DIM];
__device__ float g_k   [NHEADS * T_DIM * HD_DIM];
__device__ float g_v   [NHEADS * T_DIM * HD_DIM];
__device__ float g_gate[NHEADS * T_DIM];
__device__ float g_ctx [NROWS * D_DIM];
__device__ float g_y1  [NROWS * D_DIM];
__device__ float g_x   [NROWS * D_DIM];
__device__ float g_h   [NROWS * FF_DIM];
__device__ float g_y2  [NROWS * D_DIM];

// ---------------------------------------------------------------------------
// mma / ldmatrix helpers
// ---------------------------------------------------------------------------
__device__ __forceinline__ unsigned sm_u32(const void* p) {
    return (unsigned)__cvta_generic_to_shared(p);
}

__device__ __forceinline__ void ldsm_x4(unsigned* f, unsigned addr) {
    asm volatile("ldmatrix.sync.aligned.m8n8.x4.shared.b16 {%0,%1,%2,%3}, [%4];"
                 : "=r"(f[0]), "=r"(f[1]), "=r"(f[2]), "=r"(f[3]) : "r"(addr));
}

__device__ __forceinline__ void mma_fp16(float* d, const unsigned* a,
                                         unsigned b0, unsigned b1) {
    asm volatile(
        "mma.sync.aligned.m16n8k16.row.col.f32.f16.f16.f32 "
        "{%0,%1,%2,%3}, {%4,%5,%6,%7}, {%8,%9}, {%0,%1,%2,%3};\n"
        : "+f"(d[0]), "+f"(d[1]), "+f"(d[2]), "+f"(d[3])
        : "r"(a[0]), "r"(a[1]), "r"(a[2]), "r"(a[3]), "r"(b0), "r"(b1));
}

// ---------------------------------------------------------------------------
// fp16 tensor-core GEMM:  C = A(N x K) @ W(M x K)^T  (+ fused epilogue)
// 128x128 tile, BK=16, 256 threads (8 warps as 4x2), warp tile 32x64.
// smem rows padded to 24 halves (48B) -> conflict-free ldmatrix.
// ---------------------------------------------------------------------------
enum { E_QKV = 0, E_ADD_ALPHA = 1, E_GELU = 2 };

#define SROW 24   // halves per smem row (16 data + 8 pad)

template <int EPI>
__global__ __launch_bounds__(256, 2) void mm_fp16(
    const float* __restrict__ A,
    const float* __restrict__ W0, const float* __restrict__ W1, const float* __restrict__ W2,
    const float* __restrict__ bp0, const float* __restrict__ bp1, const float* __restrict__ bp2,
    const float* __restrict__ aux,
    float* __restrict__ C0, float* __restrict__ C1, float* __restrict__ C2,
    int K, int ldc)
{
    __shared__ alignas(16) __half As[2][128 * SROW];
    __shared__ alignas(16) __half Bs[2][128 * SROW];

    int sel = 0, mblk = blockIdx.x;
    const float* W = W0; const float* bias = bp0; float* C = C0;
    if (EPI == E_QKV) {
        sel  = blockIdx.x / 6;
        mblk = blockIdx.x % 6;
        if (sel == 1) { W = W1; bias = bp1; C = C1; }
        else if (sel == 2) { W = W2; bias = bp2; C = C2; }
    }

    const int n0 = blockIdx.y * 128;   // A-row block
    const int m0 = mblk * 128;         // W-row (output col) block
    const int tid  = threadIdx.x;
    const int lane = tid & 31;
    const int wid  = tid >> 5;
    const int wr = (wid >> 1) * 32;    // warp row offset in tile
    const int wc = (wid & 1)  * 64;    // warp col offset in tile
    const int g = lane >> 2;
    const int c = lane & 3;

    float acc[2][8][4];
#pragma unroll
    for (int mf = 0; mf < 2; mf++)
#pragma unroll
        for (int nf = 0; nf < 8; nf++)
#pragma unroll
            for (int r = 0; r < 4; r++) acc[mf][nf][r] = 0.f;

    const float* Ab = A + (size_t)n0 * K;
    const float* Wb = W + (size_t)m0 * K;

    // loader: each thread covers one 8-half segment per operand per tile
    const int lrow = tid >> 1;          // 0..127
    const int lseg = (tid & 1) * 8;     // 0 or 8

    // ldmatrix source addresses (per warp)
    //   A frag mf: rows wr+mf*16+(lane&15), k-offset (lane>>4)*8
    //   B frag bi: rows wc+bi*16+(lane&7)+((lane>>4)&1)*8, k-offset ((lane>>3)&1)*8
    const int a_row = wr + (lane & 15);
    const int a_kb  = (lane >> 4) * 8;
    const int b_row = wc + (lane & 7) + ((lane >> 4) & 1) * 8;
    const int b_kb  = ((lane >> 3) & 1) * 8;

    // --- prologue: load tile 0 ---
    float4 pa0 = *(const float4*)(Ab + (size_t)lrow * K + lseg);
    float4 pa1 = *(const float4*)(Ab + (size_t)lrow * K + lseg + 4);
    float4 pb0 = *(const float4*)(Wb + (size_t)lrow * K + lseg);
    float4 pb1 = *(const float4*)(Wb + (size_t)lrow * K + lseg + 4);
    {
        half2* da = (half2*)&As[0][lrow * SROW + lseg];
        da[0] = __floats2half2_rn(pa0.x, pa0.y);
        da[1] = __floats2half2_rn(pa0.z, pa0.w);
        da[2] = __floats2half2_rn(pa1.x, pa1.y);
        da[3] = __floats2half2_rn(pa1.z, pa1.w);
        half2* db = (half2*)&Bs[0][lrow * SROW + lseg];
        db[0] = __floats2half2_rn(pb0.x, pb0.y);
        db[1] = __floats2half2_rn(pb0.z, pb0.w);
        db[2] = __floats2half2_rn(pb1.x, pb1.y);
        db[3] = __floats2half2_rn(pb1.z, pb1.w);
    }
    __syncthreads();

    for (int kt = 0; kt < K; kt += 16) {
        const int  buf  = (kt >> 4) & 1;
        const bool more = (kt + 16) < K;

        if (more) {
            const float* Ap = Ab + (size_t)lrow * K + kt + 16 + lseg;
            const float* Wp = Wb + (size_t)lrow * K + kt + 16 + lseg;
            pa0 = *(const float4*)(Ap);
            pa1 = *(const float4*)(Ap + 4);
            pb0 = *(const float4*)(Wp);
            pb1 = *(const float4*)(Wp + 4);
        }

        // fragments
        unsigned af[2][4], bf[4][4];
        unsigned abase = sm_u32(&As[buf][a_row * SROW + a_kb]);
        ldsm_x4(af[0], abase);
        ldsm_x4(af[1], abase + 16 * SROW * 2);
        unsigned bbase = sm_u32(&Bs[buf][b_row * SROW + b_kb]);
#pragma unroll
        for (int bi = 0; bi < 4; bi++)
            ldsm_x4(bf[bi], bbase + bi * 16 * SROW * 2);

#pragma unroll
        for (int mf = 0; mf < 2; mf++)
#pragma unroll
            for (int nf = 0; nf < 8; nf++) {
                const int bi = nf >> 1, hi = (nf & 1) * 2;
                mma_fp16(acc[mf][nf], af[mf], bf[bi][hi], bf[bi][hi + 1]);
            }

        if (more) {
            half2* da = (half2*)&As[buf ^ 1][lrow * SROW + lseg];
            da[0] = __floats2half2_rn(pa0.x, pa0.y);
            da[1] = __floats2half2_rn(pa0.z, pa0.w);
            da[2] = __floats2half2_rn(pa1.x, pa1.y);
            da[3] = __floats2half2_rn(pa1.z, pa1.w);
            half2* db = (half2*)&Bs[buf ^ 1][lrow * SROW + lseg];
            db[0] = __floats2half2_rn(pb0.x, pb0.y);
            db[1] = __floats2half2_rn(pb0.z, pb0.w);
            db[2] = __floats2half2_rn(pb1.x, pb1.y);
            db[3] = __floats2half2_rn(pb1.z, pb1.w);
        }
        __syncthreads();
    }

    // Epilogue (same accumulator layout as tf32 m16n8)
#pragma unroll
    for (int mf = 0; mf < 2; mf++) {
#pragma unroll
        for (int r2 = 0; r2 < 2; r2++) {
            const int n = n0 + wr + mf * 16 + g + r2 * 8;
#pragma unroll
            for (int nf = 0; nf < 8; nf++) {
#pragma unroll
                for (int j = 0; j < 2; j++) {
                    const int m = m0 + wc + nf * 8 + c * 2 + j;
                    float v = acc[mf][nf][r2 * 2 + j] + bias[m];
                    if (EPI == E_QKV) {
                        if (sel == 0) v *= QSCALE;
                        const int t = n >> 2, b = n & 3, h = m >> 6, hd = m & 63;
                        C[(((size_t)(b * H_DIM + h) * T_DIM) + t) * HD_DIM + hd] = v;
                    } else if (EPI == E_ADD_ALPHA) {
                        C[(size_t)n * ldc + m] = v + aux[(size_t)n * ldc + m] * ALPHA_C;
                    } else { // E_GELU (exact)
                        C[(size_t)n * ldc + m] =
                            0.5f * v * (1.f + erff(v * 0.70710678118654752f));
                    }
                }
            }
        }
    }
}

// ---------------------------------------------------------------------------
// Gate kernel
// ---------------------------------------------------------------------------
__global__ void gate_kernel(const float* __restrict__ q,
                            const float* __restrict__ grep_w,
                            const float* __restrict__ grep_b,
                            const float* __restrict__ grep_a,
                            float* __restrict__ gate)
{
    const int idx  = blockIdx.x * 8 + (threadIdx.x >> 5);
    const int lane = threadIdx.x & 31;
    const int d0 = lane, d1 = lane + 32;

    float wa0 = grep_w[d0] + grep_w[64 + d0] + grep_w[128 + d0] + grep_w[192 + d0];
    float wa1 = grep_w[d1] + grep_w[64 + d1] + grep_w[128 + d1] + grep_w[192 + d1];
    float wb0 = grep_w[256 + d0] + grep_w[320 + d0] + grep_w[384 + d0] + grep_w[448 + d0];
    float wb1 = grep_w[256 + d1] + grep_w[320 + d1] + grep_w[384 + d1] + grep_w[448 + d1];

    const float* qr = q + (size_t)idx * 64;
    float q0 = qr[d0] * 256.f, q1 = qr[d1] * 256.f;
    float sa = q0 * wa0 + q1 * wa1;
    float sb = q0 * wb0 + q1 * wb1;
#pragma unroll
    for (int o = 16; o; o >>= 1) {
        sa += __shfl_xor_sync(0xffffffffu, sa, o);
        sb += __shfl_xor_sync(0xffffffffu, sb, o);
    }
    if (lane == 0) {
        sa += grep_b[0] + grep_b[1] + grep_b[2] + grep_b[3];
        sb += grep_b[4] + grep_b[5] + grep_b[6] + grep_b[7];
        float ga = 1.f / (1.f + __expf(-sa));
        float gb = 1.f / (1.f + __expf(-sb));
        int h = (idx >> 10) % H_DIM;
        gate[idx] = ga * (gb * grep_a[h] - 1.f) + 2.f;
    }
}

// ---------------------------------------------------------------------------
// Flash attention (fp32): logits = 32*(q.k) + gate*pb ; online softmax.
// ---------------------------------------------------------------------------
__global__ __launch_bounds__(256) void flash_attn(
    const float* __restrict__ q, const float* __restrict__ k,
    const float* __restrict__ v, const float* __restrict__ pb,
    const float* __restrict__ gate, float* __restrict__ ctx)
{
    extern __shared__ float sm[];
    float* Qs = sm;
    float* Kt = Qs + 4096;
    float* Vs = Kt + 4160;
    float* Ps = Vs + 4096;
    float* Gs = Ps + 4096;

    const int bh   = blockIdx.y;
    const int q0   = blockIdx.x * 64;
    const int tid  = threadIdx.x;
    const int lane = tid & 31;
    const int w    = tid >> 5;

    const float* qb = q + ((size_t)bh * T_DIM + q0) * 64;
    for (int i = tid; i < 1024; i += 256)
        ((float4*)Qs)[i] = ((const float4*)qb)[i];
    if (tid < 64) Gs[tid] = gate[bh * T_DIM + q0 + tid];

    float m[8], l[8], a0[8], a1[8];
#pragma unroll
    for (int r = 0; r < 8; r++) { m[r] = -1e30f; l[r] = 0.f; a0[r] = 0.f; a1[r] = 0.f; }

    const float* kb  = k + (size_t)bh * 65536;
    const float* vb  = v + (size_t)bh * 65536;
    const float* pbb = pb + (size_t)bh * 1048576 + (size_t)(q0 + w * 8) * 1024;
    const float* Qw  = Qs + w * 8 * 64;

    for (int ktile = 0; ktile < 16; ktile++) {
        const float* kg = kb + ktile * 4096;
#pragma unroll
        for (int it = 0; it < 16; it++) {
            int idx = it * 256 + tid;
            Kt[(idx & 63) * 65 + (idx >> 6)] = kg[idx];
        }
        const float4* vg = (const float4*)(vb + ktile * 4096);
        for (int i = tid; i < 1024; i += 256)
            ((float4*)Vs)[i] = vg[i];
        __syncthreads();

        float s0[8], s1[8];
#pragma unroll
        for (int r = 0; r < 8; r++) { s0[r] = 0.f; s1[r] = 0.f; }
#pragma unroll 8
        for (int d = 0; d < 64; d++) {
            float k0 = Kt[d * 65 + lane];
            float k1 = Kt[d * 65 + 32 + lane];
#pragma unroll
            for (int r = 0; r < 8; r++) {
                float qv = Qw[r * 64 + d];
                s0[r] += qv * k0;
                s1[r] += qv * k1;
            }
        }

        const float* pbt = pbb + ktile * 64;
#pragma unroll
        for (int r = 0; r < 8; r++) {
            float g  = Gs[w * 8 + r];
            float l0 = 32.f * s0[r] + g * pbt[(size_t)r * 1024 + lane];
            float l1 = 32.f * s1[r] + g * pbt[(size_t)r * 1024 + 32 + lane];
            float mx = fmaxf(l0, l1);
#pragma unroll
            for (int o = 16; o; o >>= 1)
                mx = fmaxf(mx, __shfl_xor_sync(0xffffffffu, mx, o));
            float mn   = fmaxf(m[r], mx);
            float p0   = __expf(l0 - mn);
            float p1   = __expf(l1 - mn);
            float corr = __expf(m[r] - mn);
            m[r] = mn;
            float ps = p0 + p1;
#pragma unroll
            for (int o = 16; o; o >>= 1)
                ps += __shfl_xor_sync(0xffffffffu, ps, o);
            l[r]  = l[r] * corr + ps;
            a0[r] *= corr;
            a1[r] *= corr;
            Ps[(w * 8 + r) * 64 + lane]      = p0;
            Ps[(w * 8 + r) * 64 + 32 + lane] = p1;
        }
        __syncwarp();

        const float* Pw = Ps + w * 8 * 64;
#pragma unroll 8
        for (int cc = 0; cc < 64; cc++) {
            float v0 = Vs[cc * 64 + lane];
            float v1 = Vs[cc * 64 + 32 + lane];
#pragma unroll
            for (int r = 0; r < 8; r++) {
                float p = Pw[r * 64 + cc];
                a0[r] += p * v0;
                a1[r] += p * v1;
            }
        }
        __syncthreads();
    }

    const int b = bh / H_DIM, hh = bh % H_DIM;
#pragma unroll
    for (int r = 0; r < 8; r++) {
        int   t   = q0 + w * 8 + r;
        float inv = 1.f / l[r];
        float* dst = ctx + ((size_t)(t * B_DIM + b)) * D_DIM + hh * 64;
        dst[lane]      = a0[r] * inv;
        dst[32 + lane] = a1[r] * inv;
    }
}

// ---------------------------------------------------------------------------
// LayerNorm
// ---------------------------------------------------------------------------
__global__ void layernorm_kernel(const float* __restrict__ in,
                                 const float* __restrict__ g,
                                 const float* __restrict__ b,
                                 float* __restrict__ out)
{
    const int row = blockIdx.x, tid = threadIdx.x;
    const float* xr = in + (size_t)row * D_DIM;
    float v0 = xr[tid], v1 = xr[tid + 256], v2 = xr[tid + 512];
    float s  = v0 + v1 + v2;
    float sq = v0 * v0 + v1 * v1 + v2 * v2;
#pragma unroll
    for (int o = 16; o; o >>= 1) {
        s  += __shfl_xor_sync(0xffffffffu, s,  o);
        sq += __shfl_xor_sync(0xffffffffu, sq, o);
    }
    __shared__ float ss[8], sqs[8], stats[2];
    const int w = tid >> 5, lane = tid & 31;
    if (lane == 0) { ss[w] = s; sqs[w] = sq; }
    __syncthreads();
    if (tid == 0) {
        float S = 0.f, SQ = 0.f;
        for (int i = 0; i < 8; i++) { S += ss[i]; SQ += sqs[i]; }
        float mu  = S * (1.f / 768.f);
        float var = SQ * (1.f / 768.f) - mu * mu;
        stats[0] = mu;
        stats[1] = rsqrtf(var + 1e-5f);
    }
    __syncthreads();
    const float mu = stats[0], rstd = stats[1];
    float* orow = out + (size_t)row * D_DIM;
    orow[tid]       = (v0 - mu) * rstd * g[tid]       + b[tid];
    orow[tid + 256] = (v1 - mu) * rstd * g[tid + 256] + b[tid + 256];
    orow[tid + 512] = (v2 - mu) * rstd * g[tid + 512] + b[tid + 512];
}

// ---------------------------------------------------------------------------
// Launch
// ---------------------------------------------------------------------------
extern "C" void kernel_launch(void* const* d_in, const int* in_sizes, int n_in,
                              void* d_out, int out_size)
{
    const float* states = (const float*)d_in[0];
    const float* pb     = (const float*)d_in[1];
    const float* Wq = (const float*)d_in[2];   const float* bq = (const float*)d_in[3];
    const float* Wk = (const float*)d_in[4];   const float* bk = (const float*)d_in[5];
    const float* Wv = (const float*)d_in[6];   const float* bv = (const float*)d_in[7];
    const float* Wo = (const float*)d_in[8];   const float* bo = (const float*)d_in[9];
    const float* grep_w = (const float*)d_in[10];
    const float* grep_b = (const float*)d_in[11];
    const float* grep_a = (const float*)d_in[12];
    const float* ln1_g  = (const float*)d_in[13];
    const float* ln1_b  = (const float*)d_in[14];
    const float* W1 = (const float*)d_in[15];  const float* b1 = (const float*)d_in[16];
    const float* W2 = (const float*)d_in[17];  const float* b2 = (const float*)d_in[18];
    const float* ln2_g  = (const float*)d_in[19];
    const float* ln2_b  = (const float*)d_in[20];
    float* out = (float*)d_out;

    float *q, *k, *v, *gate, *ctx, *y1, *x, *h, *y2;
    cudaGetSymbolAddress((void**)&q,    g_q);
    cudaGetSymbolAddress((void**)&k,    g_k);
    cudaGetSymbolAddress((void**)&v,    g_v);
    cudaGetSymbolAddress((void**)&gate, g_gate);
    cudaGetSymbolAddress((void**)&ctx,  g_ctx);
    cudaGetSymbolAddress((void**)&y1,   g_y1);
    cudaGetSymbolAddress((void**)&x,    g_x);
    cudaGetSymbolAddress((void**)&h,    g_h);
    cudaGetSymbolAddress((void**)&y2,   g_y2);

    const dim3 blk(256);

    // Fused QKV projections (fp16 tensor cores, scattered to head-major)
    mm_fp16<E_QKV><<<dim3(18, 32), blk>>>(states, Wq, Wk, Wv, bq, bk, bv,
                                          nullptr, q, k, v, D_DIM, 0);

    // gating
    gate_kernel<<<NHEADS * T_DIM / 8, blk>>>(q, grep_w, grep_b, grep_a, gate);

    // fused attention
    cudaFuncSetAttribute(flash_attn, cudaFuncAttributeMaxDynamicSharedMemorySize, 66048);
    flash_attn<<<dim3(T_DIM / 64, NHEADS), blk, 66048>>>(q, k, v, pb, gate, ctx);

    // Wo projection + residual, then LN1
    mm_fp16<E_ADD_ALPHA><<<dim3(6, 32), blk>>>(ctx, Wo, nullptr, nullptr, bo, nullptr, nullptr,
                                               states, y1, nullptr, nullptr, D_DIM, D_DIM);
    layernorm_kernel<<<NROWS, blk>>>(y1, ln1_g, ln1_b, x);

    // FFN
    mm_fp16<E_GELU><<<dim3(24, 32), blk>>>(x, W1, nullptr, nullptr, b1, nullptr, nullptr,
                                           nullptr, h, nullptr, nullptr, D_DIM, FF_DIM);
    mm_fp16<E_ADD_ALPHA><<<dim3(6, 32), blk>>>(h, W2, nullptr, nullptr, b2, nullptr, nullptr,
                                               x, y2, nullptr, nullptr, FF_DIM, D_DIM);
    layernorm_kernel<<<NROWS, blk>>>(y2, ln2_g, ln2_b, out);

    // second output: passthrough positional_bias
    cudaMemcpyAsync(out + (size_t)NROWS * D_DIM, pb,
                    (size_t)NHEADS * T_DIM * T_DIM * sizeof(float),
                    cudaMemcpyDeviceToDevice, 0);
}

// round 7
// speedup vs baseline: 4.2342x; 1.9244x over previous
#include <cuda_runtime.h>
#include <cuda_fp16.h>
#include <math.h>

// ---------------------------------------------------------------------------
// Problem constants
// ---------------------------------------------------------------------------
#define T_DIM   1024
#define B_DIM   4
#define D_DIM   768
#define H_DIM   12
#define HD_DIM  64
#define FF_DIM  3072
#define NROWS   4096          // T*B
#define NHEADS  48            // B*H
#define ALPHA_C 2.2133638394006434f   // 24^0.25
#define QSCALE  0.00390625f           // 0.125/32

// ---------------------------------------------------------------------------
// Scratch (device globals: allocation-free rule)
// ---------------------------------------------------------------------------
__device__ __half g_hstates[NROWS * D_DIM];
__device__ __half g_hWq[D_DIM * D_DIM];
__device__ __half g_hWk[D_DIM * D_DIM];
__device__ __half g_hWv[D_DIM * D_DIM];
__device__ __half g_hWo[D_DIM * D_DIM];
__device__ __half g_hW1[FF_DIM * D_DIM];
__device__ __half g_hW2[D_DIM * FF_DIM];
__device__ __half g_hq [NHEADS * T_DIM * HD_DIM];
__device__ __half g_hk [NHEADS * T_DIM * HD_DIM];
__device__ __half g_hv [NHEADS * T_DIM * HD_DIM];
__device__ __half g_hctx[NROWS * D_DIM];
__device__ __half g_hx [NROWS * D_DIM];
__device__ __half g_hh [NROWS * FF_DIM];
__device__ float  g_gate[NHEADS * T_DIM];
__device__ float  g_y1 [NROWS * D_DIM];
__device__ float  g_x  [NROWS * D_DIM];
__device__ float  g_y2 [NROWS * D_DIM];

// ---------------------------------------------------------------------------
// PTX helpers
// ---------------------------------------------------------------------------
__device__ __forceinline__ unsigned sm_u32(const void* p) {
    return (unsigned)__cvta_generic_to_shared(p);
}
__device__ __forceinline__ void cp16(void* s, const void* g) {
    asm volatile("cp.async.ca.shared.global [%0], [%1], 16;\n"
                 :: "r"(sm_u32(s)), "l"(g));
}
#define CP_COMMIT() asm volatile("cp.async.commit_group;\n")
#define CP_WAIT(N)  asm volatile("cp.async.wait_group %0;\n" :: "n"(N))

__device__ __forceinline__ void ldsm_x4(unsigned* f, unsigned addr) {
    asm volatile("ldmatrix.sync.aligned.m8n8.x4.shared.b16 {%0,%1,%2,%3}, [%4];"
                 : "=r"(f[0]), "=r"(f[1]), "=r"(f[2]), "=r"(f[3]) : "r"(addr));
}
__device__ __forceinline__ void ldsm_x4_t(unsigned* f, unsigned addr) {
    asm volatile("ldmatrix.sync.aligned.m8n8.x4.trans.shared.b16 {%0,%1,%2,%3}, [%4];"
                 : "=r"(f[0]), "=r"(f[1]), "=r"(f[2]), "=r"(f[3]) : "r"(addr));
}
__device__ __forceinline__ void mma_fp16(float* d, const unsigned* a,
                                         unsigned b0, unsigned b1) {
    asm volatile(
        "mma.sync.aligned.m16n8k16.row.col.f32.f16.f16.f32 "
        "{%0,%1,%2,%3}, {%4,%5,%6,%7}, {%8,%9}, {%0,%1,%2,%3};\n"
        : "+f"(d[0]), "+f"(d[1]), "+f"(d[2]), "+f"(d[3])
        : "r"(a[0]), "r"(a[1]), "r"(a[2]), "r"(a[3]), "r"(b0), "r"(b1));
}

// ---------------------------------------------------------------------------
// fp32 -> fp16 conversion of states + all 6 weight matrices (one launch)
// ---------------------------------------------------------------------------
__global__ void f2h_all(const float* __restrict__ s0, const float* __restrict__ wq,
                        const float* __restrict__ wk, const float* __restrict__ wv,
                        const float* __restrict__ wo, const float* __restrict__ w1,
                        const float* __restrict__ w2)
{
    const int total4 = 2555904;  // 10,223,616 floats / 4
    for (int i = blockIdx.x * blockDim.x + threadIdx.x; i < total4;
         i += gridDim.x * blockDim.x) {
        int f = i * 4;
        const float* src; __half* dst; int off;
        if      (f < 3145728) { src = s0; dst = g_hstates; off = f; }
        else if (f < 3735552) { src = wq; dst = g_hWq; off = f - 3145728; }
        else if (f < 4325376) { src = wk; dst = g_hWk; off = f - 3735552; }
        else if (f < 4915200) { src = wv; dst = g_hWv; off = f - 4325376; }
        else if (f < 5505024) { src = wo; dst = g_hWo; off = f - 4915200; }
        else if (f < 7864320) { src = w1; dst = g_hW1; off = f - 5505024; }
        else                  { src = w2; dst = g_hW2; off = f - 7864320; }
        float4 v = *(const float4*)(src + off);
        half2* d = (half2*)(dst + off);
        d[0] = __floats2half2_rn(v.x, v.y);
        d[1] = __floats2half2_rn(v.z, v.w);
    }
}

// ---------------------------------------------------------------------------
// fp16 tensor-core GEMM with 5-stage cp.async pipeline.
// C = A(N x K) @ W(M x K)^T  (+ fused epilogue)
// 128x128 tile, BK=16, 256 threads (8 warps as 4x2), warp tile 32x64.
// ---------------------------------------------------------------------------
enum { E_QKV = 0, E_ADD_ALPHA = 1, E_GELU = 2 };

#define SROW   24        // halves per smem row (16 data + 8 pad)
#define STAGES 5
#define STG_H  (128 * SROW)                 // halves per operand per stage
#define MM_SMEM (2 * STAGES * STG_H * 2)    // bytes

template <int EPI>
__global__ __launch_bounds__(256, 2) void mm_h(
    const __half* __restrict__ A,
    const __half* __restrict__ W0, const __half* __restrict__ W1h, const __half* __restrict__ W2h,
    const float* __restrict__ bp0, const float* __restrict__ bp1, const float* __restrict__ bp2,
    const float* __restrict__ aux,
    void* __restrict__ C0, void* __restrict__ C1, void* __restrict__ C2,
    int K, int ldc)
{
    extern __shared__ __half smh[];
    __half* Asm = smh;                     // STAGES * STG_H
    __half* Bsm = smh + STAGES * STG_H;

    int sel = 0, mblk = blockIdx.x;
    const __half* W = W0; const float* bias = bp0; void* C = C0;
    if (EPI == E_QKV) {
        sel  = blockIdx.x / 6;
        mblk = blockIdx.x % 6;
        if (sel == 1) { W = W1h; bias = bp1; C = C1; }
        else if (sel == 2) { W = W2h; bias = bp2; C = C2; }
    }

    const int n0 = blockIdx.y * 128;
    const int m0 = mblk * 128;
    const int tid  = threadIdx.x;
    const int lane = tid & 31;
    const int wid  = tid >> 5;
    const int wr = (wid >> 1) * 32;
    const int wc = (wid & 1)  * 64;
    const int g = lane >> 2;
    const int c = lane & 3;

    float acc[2][8][4];
#pragma unroll
    for (int mf = 0; mf < 2; mf++)
#pragma unroll
        for (int nf = 0; nf < 8; nf++)
#pragma unroll
            for (int r = 0; r < 4; r++) acc[mf][nf][r] = 0.f;

    const __half* Ab = A + (size_t)n0 * K;
    const __half* Wb = W + (size_t)m0 * K;

    const int lrow = tid >> 1;         // 0..127
    const int lch  = (tid & 1) * 8;    // halves: 0 or 8

    const int NK = K >> 4;

    // prologue: stages 0..3
#pragma unroll
    for (int s = 0; s < 4; s++) {
        cp16(&Asm[s * STG_H + lrow * SROW + lch], Ab + (size_t)lrow * K + s * 16 + lch);
        cp16(&Bsm[s * STG_H + lrow * SROW + lch], Wb + (size_t)lrow * K + s * 16 + lch);
        CP_COMMIT();
    }

    const int a_row = wr + (lane & 15);
    const int a_kb  = (lane >> 4) * 8;
    const int b_row = wc + (lane & 7) + ((lane >> 4) & 1) * 8;
    const int b_kb  = ((lane >> 3) & 1) * 8;

    for (int i = 0; i < NK; i++) {
        const int s   = i % STAGES;
        const int rem = NK - i - 1;
        if      (rem >= 3) CP_WAIT(3);
        else if (rem == 2) CP_WAIT(2);
        else if (rem == 1) CP_WAIT(1);
        else               CP_WAIT(0);
        __syncthreads();

        unsigned af[2][4], bf[4][4];
        unsigned abase = sm_u32(&Asm[s * STG_H + a_row * SROW + a_kb]);
        ldsm_x4(af[0], abase);
        ldsm_x4(af[1], abase + 16 * SROW * 2);
        unsigned bbase = sm_u32(&Bsm[s * STG_H + b_row * SROW + b_kb]);
#pragma unroll
        for (int bi = 0; bi < 4; bi++)
            ldsm_x4(bf[bi], bbase + bi * 16 * SROW * 2);

#pragma unroll
        for (int mf = 0; mf < 2; mf++)
#pragma unroll
            for (int nf = 0; nf < 8; nf++) {
                const int bi = nf >> 1, hi = (nf & 1) * 2;
                mma_fp16(acc[mf][nf], af[mf], bf[bi][hi], bf[bi][hi + 1]);
            }
        __syncthreads();

        if (i + 4 < NK) {
            const int s2 = (i + 4) % STAGES;
            const int kt = (i + 4) * 16;
            cp16(&Asm[s2 * STG_H + lrow * SROW + lch], Ab + (size_t)lrow * K + kt + lch);
            cp16(&Bsm[s2 * STG_H + lrow * SROW + lch], Wb + (size_t)lrow * K + kt + lch);
            CP_COMMIT();
        }
    }

    // Epilogue
#pragma unroll
    for (int mf = 0; mf < 2; mf++) {
#pragma unroll
        for (int r2 = 0; r2 < 2; r2++) {
            const int n = n0 + wr + mf * 16 + g + r2 * 8;
#pragma unroll
            for (int nf = 0; nf < 8; nf++) {
#pragma unroll
                for (int j = 0; j < 2; j++) {
                    const int m = m0 + wc + nf * 8 + c * 2 + j;
                    float v = acc[mf][nf][r2 * 2 + j] + bias[m];
                    if (EPI == E_QKV) {
                        if (sel == 0) v *= QSCALE;
                        const int t = n >> 2, b = n & 3, h = m >> 6, hd = m & 63;
                        ((__half*)C)[(((size_t)(b * H_DIM + h) * T_DIM) + t) * HD_DIM + hd] =
                            __float2half_rn(v);
                    } else if (EPI == E_ADD_ALPHA) {
                        ((float*)C)[(size_t)n * ldc + m] =
                            v + aux[(size_t)n * ldc + m] * ALPHA_C;
                    } else { // E_GELU (exact) -> fp16
                        ((__half*)C)[(size_t)n * ldc + m] = __float2half_rn(
                            0.5f * v * (1.f + erff(v * 0.70710678118654752f)));
                    }
                }
            }
        }
    }
}

// ---------------------------------------------------------------------------
// Gate kernel (reads fp16 q)
// ---------------------------------------------------------------------------
__global__ void gate_kernel(const __half* __restrict__ q,
                            const float* __restrict__ grep_w,
                            const float* __restrict__ grep_b,
                            const float* __restrict__ grep_a,
                            float* __restrict__ gate)
{
    const int idx  = blockIdx.x * 8 + (threadIdx.x >> 5);
    const int lane = threadIdx.x & 31;
    const int d0 = lane, d1 = lane + 32;

    float wa0 = grep_w[d0] + grep_w[64 + d0] + grep_w[128 + d0] + grep_w[192 + d0];
    float wa1 = grep_w[d1] + grep_w[64 + d1] + grep_w[128 + d1] + grep_w[192 + d1];
    float wb0 = grep_w[256 + d0] + grep_w[320 + d0] + grep_w[384 + d0] + grep_w[448 + d0];
    float wb1 = grep_w[256 + d1] + grep_w[320 + d1] + grep_w[384 + d1] + grep_w[448 + d1];

    const __half* qr = q + (size_t)idx * 64;
    float q0 = __half2float(qr[d0]) * 256.f, q1 = __half2float(qr[d1]) * 256.f;
    float sa = q0 * wa0 + q1 * wa1;
    float sb = q0 * wb0 + q1 * wb1;
#pragma unroll
    for (int o = 16; o; o >>= 1) {
        sa += __shfl_xor_sync(0xffffffffu, sa, o);
        sb += __shfl_xor_sync(0xffffffffu, sb, o);
    }
    if (lane == 0) {
        sa += grep_b[0] + grep_b[1] + grep_b[2] + grep_b[3];
        sb += grep_b[4] + grep_b[5] + grep_b[6] + grep_b[7];
        float ga = 1.f / (1.f + __expf(-sa));
        float gb = 1.f / (1.f + __expf(-sb));
        int h = (idx >> 10) % H_DIM;
        gate[idx] = ga * (gb * grep_a[h] - 1.f) + 2.f;
    }
}

// ---------------------------------------------------------------------------
// Tensor-core flash attention.
// Grid (8, 48): 128 q-rows per CTA, 8 warps each owning 16 rows.
// logits = 32*(q.k) + gate*pb ; warp-local online softmax; fp16 MMAs.
// smem: Q 128x72h | K 2x64x72h | V 2x64x72h | gates 128f
// ---------------------------------------------------------------------------
#define FA_QH   (128 * 72)
#define FA_KVH  (64 * 72)
#define FA_SMEM ((FA_QH + 4 * FA_KVH) * 2 + 512)

__global__ __launch_bounds__(256, 2) void flash_attn_h(
    const __half* __restrict__ q, const __half* __restrict__ k,
    const __half* __restrict__ v, const float* __restrict__ pb,
    const float* __restrict__ gate, __half* __restrict__ ctx)
{
    extern __shared__ __half smh[];
    __half* Qs = smh;
    __half* Ks = smh + FA_QH;                 // 2 stages
    __half* Vs = smh + FA_QH + 2 * FA_KVH;    // 2 stages
    float*  Gs = (float*)(smh + FA_QH + 4 * FA_KVH);

    const int bh   = blockIdx.y;
    const int q0   = blockIdx.x * 128;
    const int tid  = threadIdx.x;
    const int lane = tid & 31;
    const int w    = tid >> 5;
    const int g    = lane >> 2;
    const int c    = lane & 3;

    const __half* qg = q + ((size_t)bh * T_DIM + q0) * 64;
    const __half* kg = k + (size_t)bh * 65536;
    const __half* vg = v + (size_t)bh * 65536;

    // group 0: Q + K/V tile 0 ; group 1: K/V tile 1
#pragma unroll
    for (int i = tid; i < 1024; i += 256) {
        int row = i >> 3, ch = (i & 7) * 8;
        cp16(&Qs[row * 72 + ch], qg + row * 64 + ch);
    }
#pragma unroll
    for (int i = tid; i < 512; i += 256) {
        int row = i >> 3, ch = (i & 7) * 8;
        cp16(&Ks[row * 72 + ch], kg + row * 64 + ch);
        cp16(&Vs[row * 72 + ch], vg + row * 64 + ch);
    }
    CP_COMMIT();
#pragma unroll
    for (int i = tid; i < 512; i += 256) {
        int row = i >> 3, ch = (i & 7) * 8;
        cp16(&Ks[FA_KVH + row * 72 + ch], kg + 4096 + row * 64 + ch);
        cp16(&Vs[FA_KVH + row * 72 + ch], vg + 4096 + row * 64 + ch);
    }
    CP_COMMIT();
    if (tid < 128) Gs[tid] = gate[bh * T_DIM + q0 + tid];

    CP_WAIT(1);
    __syncthreads();

    // Q fragments (persist in registers)
    unsigned af[4][4];
    {
        const int ar  = w * 16 + (lane & 15);
        const int akb = (lane >> 4) * 8;
#pragma unroll
        for (int ks = 0; ks < 4; ks++)
            ldsm_x4(af[ks], sm_u32(&Qs[ar * 72 + ks * 16 + akb]));
    }

    float m0 = -1e30f, m1 = -1e30f, l0 = 0.f, l1 = 0.f;
    float oacc[8][4];
#pragma unroll
    for (int hb = 0; hb < 8; hb++)
#pragma unroll
        for (int j = 0; j < 4; j++) oacc[hb][j] = 0.f;

    const float gr0 = Gs[w * 16 + g];
    const float gr1 = Gs[w * 16 + g + 8];
    const float* pbr0 = pb + ((size_t)bh * T_DIM + q0 + w * 16 + g) * T_DIM;

    const int brow = (lane & 7) + ((lane >> 4) & 1) * 8;
    const int bkb  = ((lane >> 3) & 1) * 8;
    const int vr   = lane & 15;
    const int vcb  = (lane >> 4) * 8;

    for (int t = 0; t < 16; t++) {
        const int buf = t & 1;
        if (t) {
            if (t < 15) CP_WAIT(1); else CP_WAIT(0);
            __syncthreads();
        }
        const __half* Kb = Ks + buf * FA_KVH;
        const __half* Vb = Vs + buf * FA_KVH;

        // S = Q @ K^T  (this warp's 16 rows x 64 keys)
        float sacc[8][4];
#pragma unroll
        for (int nb = 0; nb < 8; nb++)
#pragma unroll
            for (int j = 0; j < 4; j++) sacc[nb][j] = 0.f;

#pragma unroll
        for (int nb2 = 0; nb2 < 4; nb2++) {
#pragma unroll
            for (int ks = 0; ks < 4; ks++) {
                unsigned bf[4];
                ldsm_x4(bf, sm_u32(&Kb[(nb2 * 16 + brow) * 72 + ks * 16 + bkb]));
                mma_fp16(sacc[nb2 * 2],     af[ks], bf[0], bf[1]);
                mma_fp16(sacc[nb2 * 2 + 1], af[ks], bf[2], bf[3]);
            }
        }

        // logits (in place) + row max
        const float* pbc = pbr0 + t * 64;
        float mx0 = -1e30f, mx1 = -1e30f;
#pragma unroll
        for (int nb = 0; nb < 8; nb++) {
            float2 p0 = *(const float2*)(pbc + nb * 8 + c * 2);
            float2 p1 = *(const float2*)(pbc + 8 * T_DIM + nb * 8 + c * 2);
            sacc[nb][0] = 32.f * sacc[nb][0] + gr0 * p0.x;
            sacc[nb][1] = 32.f * sacc[nb][1] + gr0 * p0.y;
            sacc[nb][2] = 32.f * sacc[nb][2] + gr1 * p1.x;
            sacc[nb][3] = 32.f * sacc[nb][3] + gr1 * p1.y;
            mx0 = fmaxf(mx0, fmaxf(sacc[nb][0], sacc[nb][1]));
            mx1 = fmaxf(mx1, fmaxf(sacc[nb][2], sacc[nb][3]));
        }
        mx0 = fmaxf(mx0, __shfl_xor_sync(0xffffffffu, mx0, 1));
        mx0 = fmaxf(mx0, __shfl_xor_sync(0xffffffffu, mx0, 2));
        mx1 = fmaxf(mx1, __shfl_xor_sync(0xffffffffu, mx1, 1));
        mx1 = fmaxf(mx1, __shfl_xor_sync(0xffffffffu, mx1, 2));

        const float nm0 = fmaxf(m0, mx0), nm1 = fmaxf(m1, mx1);
        const float corr0 = __expf(m0 - nm0), corr1 = __expf(m1 - nm1);
        m0 = nm0; m1 = nm1;

        // exp -> fp16 P fragments ; row sums
        unsigned pa[4][4];
        float s0 = 0.f, s1 = 0.f;
#pragma unroll
        for (int nb = 0; nb < 8; nb++) {
            float e0 = __expf(sacc[nb][0] - nm0);
            float e1 = __expf(sacc[nb][1] - nm0);
            float e2 = __expf(sacc[nb][2] - nm1);
            float e3 = __expf(sacc[nb][3] - nm1);
            s0 += e0 + e1; s1 += e2 + e3;
            const int kp = nb >> 1, off = (nb & 1) * 2;
            half2 h0 = __floats2half2_rn(e0, e1);
            half2 h1 = __floats2half2_rn(e2, e3);
            pa[kp][off]     = *(unsigned*)&h0;
            pa[kp][off + 1] = *(unsigned*)&h1;
        }
        s0 += __shfl_xor_sync(0xffffffffu, s0, 1);
        s0 += __shfl_xor_sync(0xffffffffu, s0, 2);
        s1 += __shfl_xor_sync(0xffffffffu, s1, 1);
        s1 += __shfl_xor_sync(0xffffffffu, s1, 2);
        l0 = l0 * corr0 + s0;
        l1 = l1 * corr1 + s1;

        // rescale output accumulators
#pragma unroll
        for (int hb = 0; hb < 8; hb++) {
            oacc[hb][0] *= corr0; oacc[hb][1] *= corr0;
            oacc[hb][2] *= corr1; oacc[hb][3] *= corr1;
        }

        // out += P @ V   (V loaded transposed)
#pragma unroll
        for (int kp = 0; kp < 4; kp++) {
#pragma unroll
            for (int hb2 = 0; hb2 < 4; hb2++) {
                unsigned bv[4];
                ldsm_x4_t(bv, sm_u32(&Vb[(kp * 16 + vr) * 72 + hb2 * 16 + vcb]));
                mma_fp16(oacc[hb2 * 2],     pa[kp], bv[0], bv[1]);
                mma_fp16(oacc[hb2 * 2 + 1], pa[kp], bv[2], bv[3]);
            }
        }
        __syncthreads();

        // prefetch K/V tile t+2
        if (t + 2 < 16) {
            const __half* ks2 = kg + (t + 2) * 4096;
            const __half* vs2 = vg + (t + 2) * 4096;
            __half* kd = Ks + buf * FA_KVH;
            __half* vd = Vs + buf * FA_KVH;
#pragma unroll
            for (int i = tid; i < 512; i += 256) {
                int row = i >> 3, ch = (i & 7) * 8;
                cp16(&kd[row * 72 + ch], ks2 + row * 64 + ch);
                cp16(&vd[row * 72 + ch], vs2 + row * 64 + ch);
            }
            CP_COMMIT();
        }
    }

    // write ctx (fp16, (T,B,D) layout) for Wo GEMM
    const float i0 = 1.f / l0, i1 = 1.f / l1;
    const int b = bh / H_DIM, hh = bh % H_DIM;
    const int t0g = q0 + w * 16 + g;
#pragma unroll
    for (int hb = 0; hb < 8; hb++) {
        const int col = hh * 64 + hb * 8 + c * 2;
        half2 o0 = __floats2half2_rn(oacc[hb][0] * i0, oacc[hb][1] * i0);
        half2 o1 = __floats2half2_rn(oacc[hb][2] * i1, oacc[hb][3] * i1);
        *(half2*)&ctx[(size_t)(t0g * B_DIM + b) * D_DIM + col]       = o0;
        *(half2*)&ctx[(size_t)((t0g + 8) * B_DIM + b) * D_DIM + col] = o1;
    }
}

// ---------------------------------------------------------------------------
// LayerNorm (optionally also emits fp16)
// ---------------------------------------------------------------------------
__global__ void layernorm_kernel(const float* __restrict__ in,
                                 const float* __restrict__ g,
                                 const float* __restrict__ b,
                                 float* __restrict__ out,
                                 __half* __restrict__ hout)
{
    const int row = blockIdx.x, tid = threadIdx.x;
    const float* xr = in + (size_t)row * D_DIM;
    float v0 = xr[tid], v1 = xr[tid + 256], v2 = xr[tid + 512];
    float s  = v0 + v1 + v2;
    float sq = v0 * v0 + v1 * v1 + v2 * v2;
#pragma unroll
    for (int o = 16; o; o >>= 1) {
        s  += __shfl_xor_sync(0xffffffffu, s,  o);
        sq += __shfl_xor_sync(0xffffffffu, sq, o);
    }
    __shared__ float ss[8], sqs[8], stats[2];
    const int w = tid >> 5, lane = tid & 31;
    if (lane == 0) { ss[w] = s; sqs[w] = sq; }
    __syncthreads();
    if (tid == 0) {
        float S = 0.f, SQ = 0.f;
        for (int i = 0; i < 8; i++) { S += ss[i]; SQ += sqs[i]; }
        float mu  = S * (1.f / 768.f);
        float var = SQ * (1.f / 768.f) - mu * mu;
        stats[0] = mu;
        stats[1] = rsqrtf(var + 1e-5f);
    }
    __syncthreads();
    const float mu = stats[0], rstd = stats[1];
    float r0 = (v0 - mu) * rstd * g[tid]       + b[tid];
    float r1 = (v1 - mu) * rstd * g[tid + 256] + b[tid + 256];
    float r2 = (v2 - mu) * rstd * g[tid + 512] + b[tid + 512];
    float* orow = out + (size_t)row * D_DIM;
    orow[tid] = r0; orow[tid + 256] = r1; orow[tid + 512] = r2;
    if (hout) {
        __half* hrow = hout + (size_t)row * D_DIM;
        hrow[tid] = __float2half_rn(r0);
        hrow[tid + 256] = __float2half_rn(r1);
        hrow[tid + 512] = __float2half_rn(r2);
    }
}

// ---------------------------------------------------------------------------
// Launch
// ---------------------------------------------------------------------------
extern "C" void kernel_launch(void* const* d_in, const int* in_sizes, int n_in,
                              void* d_out, int out_size)
{
    const float* states = (const float*)d_in[0];
    const float* pb     = (const float*)d_in[1];
    const float* Wq = (const float*)d_in[2];   const float* bq = (const float*)d_in[3];
    const float* Wk = (const float*)d_in[4];   const float* bk = (const float*)d_in[5];
    const float* Wv = (const float*)d_in[6];   const float* bv = (const float*)d_in[7];
    const float* Wo = (const float*)d_in[8];   const float* bo = (const float*)d_in[9];
    const float* grep_w = (const float*)d_in[10];
    const float* grep_b = (const float*)d_in[11];
    const float* grep_a = (const float*)d_in[12];
    const float* ln1_g  = (const float*)d_in[13];
    const float* ln1_b  = (const float*)d_in[14];
    const float* W1 = (const float*)d_in[15];  const float* b1 = (const float*)d_in[16];
    const float* W2 = (const float*)d_in[17];  const float* b2 = (const float*)d_in[18];
    const float* ln2_g  = (const float*)d_in[19];
    const float* ln2_b  = (const float*)d_in[20];
    float* out = (float*)d_out;

    __half *hstates, *hWq, *hWk, *hWv, *hWo, *hW1, *hW2;
    __half *hq, *hk, *hv, *hctx, *hx, *hh;
    float  *gate, *y1, *x, *y2;
    cudaGetSymbolAddress((void**)&hstates, g_hstates);
    cudaGetSymbolAddress((void**)&hWq, g_hWq);
    cudaGetSymbolAddress((void**)&hWk, g_hWk);
    cudaGetSymbolAddress((void**)&hWv, g_hWv);
    cudaGetSymbolAddress((void**)&hWo, g_hWo);
    cudaGetSymbolAddress((void**)&hW1, g_hW1);
    cudaGetSymbolAddress((void**)&hW2, g_hW2);
    cudaGetSymbolAddress((void**)&hq,  g_hq);
    cudaGetSymbolAddress((void**)&hk,  g_hk);
    cudaGetSymbolAddress((void**)&hv,  g_hv);
    cudaGetSymbolAddress((void**)&hctx, g_hctx);
    cudaGetSymbolAddress((void**)&hx,  g_hx);
    cudaGetSymbolAddress((void**)&hh,  g_hh);
    cudaGetSymbolAddress((void**)&gate, g_gate);
    cudaGetSymbolAddress((void**)&y1,  g_y1);
    cudaGetSymbolAddress((void**)&x,   g_x);
    cudaGetSymbolAddress((void**)&y2,  g_y2);

    cudaFuncSetAttribute(mm_h<E_QKV>,      cudaFuncAttributeMaxDynamicSharedMemorySize, MM_SMEM);
    cudaFuncSetAttribute(mm_h<E_ADD_ALPHA>,cudaFuncAttributeMaxDynamicSharedMemorySize, MM_SMEM);
    cudaFuncSetAttribute(mm_h<E_GELU>,     cudaFuncAttributeMaxDynamicSharedMemorySize, MM_SMEM);
    cudaFuncSetAttribute(flash_attn_h,     cudaFuncAttributeMaxDynamicSharedMemorySize, FA_SMEM);

    const dim3 blk(256);

    // fp32 -> fp16 for states + weights
    f2h_all<<<2496, blk>>>(states, Wq, Wk, Wv, Wo, W1, W2);

    // Fused QKV projections (fp16 tensor cores, scattered to head-major fp16)
    mm_h<E_QKV><<<dim3(18, 32), blk, MM_SMEM>>>(
        hstates, hWq, hWk, hWv, bq, bk, bv, nullptr, hq, hk, hv, D_DIM, 0);

    // gating
    gate_kernel<<<NHEADS * T_DIM / 8, blk>>>(hq, grep_w, grep_b, grep_a, gate);

    // tensor-core flash attention
    flash_attn_h<<<dim3(T_DIM / 128, NHEADS), blk, FA_SMEM>>>(hq, hk, hv, pb, gate, hctx);

    // Wo projection + residual (fp32 aux), then LN1 (fp32 + fp16 out)
    mm_h<E_ADD_ALPHA><<<dim3(6, 32), blk, MM_SMEM>>>(
        hctx, hWo, nullptr, nullptr, bo, nullptr, nullptr,
        states, y1, nullptr, nullptr, D_DIM, D_DIM);
    layernorm_kernel<<<NROWS, blk>>>(y1, ln1_g, ln1_b, x, hx);

    // FFN
    mm_h<E_GELU><<<dim3(24, 32), blk, MM_SMEM>>>(
        hx, hW1, nullptr, nullptr, b1, nullptr, nullptr,
        nullptr, hh, nullptr, nullptr, D_DIM, FF_DIM);
    mm_h<E_ADD_ALPHA><<<dim3(6, 32), blk, MM_SMEM>>>(
        hh, hW2, nullptr, nullptr, b2, nullptr, nullptr,
        x, y2, nullptr, nullptr, FF_DIM, D_DIM);
    layernorm_kernel<<<NROWS, blk>>>(y2, ln2_g, ln2_b, out, nullptr);

    // second output: passthrough positional_bias
    cudaMemcpyAsync(out + (size_t)NROWS * D_DIM, pb,
                    (size_t)NHEADS * T_DIM * T_DIM * sizeof(float),
                    cudaMemcpyDeviceToDevice, 0);
}

// round 8
// speedup vs baseline: 5.3456x; 1.2625x over previous
#include <cuda_runtime.h>
#include <cuda_fp16.h>
#include <math.h>

// ---------------------------------------------------------------------------
// Problem constants
// ---------------------------------------------------------------------------
#define T_DIM   1024
#define B_DIM   4
#define D_DIM   768
#define H_DIM   12
#define HD_DIM  64
#define FF_DIM  3072
#define NROWS   4096          // T*B
#define NHEADS  48            // B*H
#define ALPHA_C 2.2133638394006434f   // 24^0.25
#define QSCALE  0.00390625f           // 0.125/32

// ---------------------------------------------------------------------------
// Scratch (device globals: allocation-free rule)
// ---------------------------------------------------------------------------
__device__ __half g_hstates[NROWS * D_DIM];
__device__ __half g_hWq[D_DIM * D_DIM];
__device__ __half g_hWk[D_DIM * D_DIM];
__device__ __half g_hWv[D_DIM * D_DIM];
__device__ __half g_hWo[D_DIM * D_DIM];
__device__ __half g_hW1[FF_DIM * D_DIM];
__device__ __half g_hW2[D_DIM * FF_DIM];
__device__ __half g_hq [NHEADS * T_DIM * HD_DIM];
__device__ __half g_hk [NHEADS * T_DIM * HD_DIM];
__device__ __half g_hv [NHEADS * T_DIM * HD_DIM];
__device__ __half g_hctx[NROWS * D_DIM];
__device__ __half g_hx [NROWS * D_DIM];
__device__ __half g_hh [NROWS * FF_DIM];
__device__ float  g_gate[NHEADS * T_DIM];
__device__ float  g_y1 [NROWS * D_DIM];
__device__ float  g_x  [NROWS * D_DIM];
__device__ float  g_y2 [NROWS * D_DIM];

// ---------------------------------------------------------------------------
// PTX helpers
// ---------------------------------------------------------------------------
__device__ __forceinline__ unsigned sm_u32(const void* p) {
    return (unsigned)__cvta_generic_to_shared(p);
}
__device__ __forceinline__ void cp16(void* s, const void* g) {
    asm volatile("cp.async.ca.shared.global [%0], [%1], 16;\n"
                 :: "r"(sm_u32(s)), "l"(g));
}
#define CP_COMMIT() asm volatile("cp.async.commit_group;\n")
#define CP_WAIT(N)  asm volatile("cp.async.wait_group %0;\n" :: "n"(N))

__device__ __forceinline__ void ldsm_x4(unsigned* f, unsigned addr) {
    asm volatile("ldmatrix.sync.aligned.m8n8.x4.shared.b16 {%0,%1,%2,%3}, [%4];"
                 : "=r"(f[0]), "=r"(f[1]), "=r"(f[2]), "=r"(f[3]) : "r"(addr));
}
__device__ __forceinline__ void ldsm_x4_t(unsigned* f, unsigned addr) {
    asm volatile("ldmatrix.sync.aligned.m8n8.x4.trans.shared.b16 {%0,%1,%2,%3}, [%4];"
                 : "=r"(f[0]), "=r"(f[1]), "=r"(f[2]), "=r"(f[3]) : "r"(addr));
}
__device__ __forceinline__ void mma_fp16(float* d, const unsigned* a,
                                         unsigned b0, unsigned b1) {
    asm volatile(
        "mma.sync.aligned.m16n8k16.row.col.f32.f16.f16.f32 "
        "{%0,%1,%2,%3}, {%4,%5,%6,%7}, {%8,%9}, {%0,%1,%2,%3};\n"
        : "+f"(d[0]), "+f"(d[1]), "+f"(d[2]), "+f"(d[3])
        : "r"(a[0]), "r"(a[1]), "r"(a[2]), "r"(a[3]), "r"(b0), "r"(b1));
}

// ---------------------------------------------------------------------------
// fp32 -> fp16 conversion of states + all 6 weight matrices (one launch)
// ---------------------------------------------------------------------------
__global__ void f2h_all(const float* __restrict__ s0, const float* __restrict__ wq,
                        const float* __restrict__ wk, const float* __restrict__ wv,
                        const float* __restrict__ wo, const float* __restrict__ w1,
                        const float* __restrict__ w2)
{
    const int total4 = 2555904;  // 10,223,616 floats / 4
    for (int i = blockIdx.x * blockDim.x + threadIdx.x; i < total4;
         i += gridDim.x * blockDim.x) {
        int f = i * 4;
        const float* src; __half* dst; int off;
        if      (f < 3145728) { src = s0; dst = g_hstates; off = f; }
        else if (f < 3735552) { src = wq; dst = g_hWq; off = f - 3145728; }
        else if (f < 4325376) { src = wk; dst = g_hWk; off = f - 3735552; }
        else if (f < 4915200) { src = wv; dst = g_hWv; off = f - 4325376; }
        else if (f < 5505024) { src = wo; dst = g_hWo; off = f - 4915200; }
        else if (f < 7864320) { src = w1; dst = g_hW1; off = f - 5505024; }
        else                  { src = w2; dst = g_hW2; off = f - 7864320; }
        float4 v = *(const float4*)(src + off);
        half2* d = (half2*)(dst + off);
        d[0] = __floats2half2_rn(v.x, v.y);
        d[1] = __floats2half2_rn(v.z, v.w);
    }
}

// ---------------------------------------------------------------------------
// fp16 tensor-core GEMM with 5-stage cp.async pipeline (1 barrier / k-iter).
// C = A(N x K) @ W(M x K)^T  (+ fused epilogue)
// 128x128 tile, BK=16, 256 threads (8 warps as 4x2), warp tile 32x64.
// ---------------------------------------------------------------------------
enum { E_QKV = 0, E_ADD_ALPHA = 1, E_GELU = 2 };

#define SROW   24        // halves per smem row (16 data + 8 pad)
#define STAGES 5
#define STG_H  (128 * SROW)                 // halves per operand per stage
#define MM_SMEM (2 * STAGES * STG_H * 2)    // bytes

template <int EPI>
__global__ __launch_bounds__(256, 2) void mm_h(
    const __half* __restrict__ A,
    const __half* __restrict__ W0, const __half* __restrict__ W1h, const __half* __restrict__ W2h,
    const float* __restrict__ bp0, const float* __restrict__ bp1, const float* __restrict__ bp2,
    const float* __restrict__ aux,
    void* __restrict__ C0, void* __restrict__ C1, void* __restrict__ C2,
    int K, int ldc)
{
    extern __shared__ __half smh[];
    __half* Asm = smh;                     // STAGES * STG_H
    __half* Bsm = smh + STAGES * STG_H;

    int sel = 0, mblk = blockIdx.x;
    const __half* W = W0; const float* bias = bp0; void* C = C0;
    if (EPI == E_QKV) {
        sel  = blockIdx.x / 6;
        mblk = blockIdx.x % 6;
        if (sel == 1) { W = W1h; bias = bp1; C = C1; }
        else if (sel == 2) { W = W2h; bias = bp2; C = C2; }
    }

    const int n0 = blockIdx.y * 128;
    const int m0 = mblk * 128;
    const int tid  = threadIdx.x;
    const int lane = tid & 31;
    const int wid  = tid >> 5;
    const int wr = (wid >> 1) * 32;
    const int wc = (wid & 1)  * 64;
    const int g = lane >> 2;
    const int c = lane & 3;

    float acc[2][8][4];
#pragma unroll
    for (int mf = 0; mf < 2; mf++)
#pragma unroll
        for (int nf = 0; nf < 8; nf++)
#pragma unroll
            for (int r = 0; r < 4; r++) acc[mf][nf][r] = 0.f;

    const __half* Ab = A + (size_t)n0 * K;
    const __half* Wb = W + (size_t)m0 * K;

    const int lrow = tid >> 1;         // 0..127
    const int lch  = (tid & 1) * 8;    // halves: 0 or 8

    const int NK = K >> 4;

    // prologue: stages 0..3
#pragma unroll
    for (int s = 0; s < 4; s++) {
        cp16(&Asm[s * STG_H + lrow * SROW + lch], Ab + (size_t)lrow * K + s * 16 + lch);
        cp16(&Bsm[s * STG_H + lrow * SROW + lch], Wb + (size_t)lrow * K + s * 16 + lch);
        CP_COMMIT();
    }

    const int a_row = wr + (lane & 15);
    const int a_kb  = (lane >> 4) * 8;
    const int b_row = wc + (lane & 7) + ((lane >> 4) & 1) * 8;
    const int b_kb  = ((lane >> 3) & 1) * 8;

    for (int i = 0; i < NK; i++) {
        const int s   = i % STAGES;
        const int rem = NK - i - 1;
        if      (rem >= 3) CP_WAIT(3);
        else if (rem == 2) CP_WAIT(2);
        else if (rem == 1) CP_WAIT(1);
        else               CP_WAIT(0);
        __syncthreads();   // data visible; all warps done with stage (i-1)%5

        // issue next stage early (overlaps with ldsm+mma below)
        if (i + 4 < NK) {
            const int s2 = (i + 4) % STAGES;
            const int kt = (i + 4) * 16;
            cp16(&Asm[s2 * STG_H + lrow * SROW + lch], Ab + (size_t)lrow * K + kt + lch);
            cp16(&Bsm[s2 * STG_H + lrow * SROW + lch], Wb + (size_t)lrow * K + kt + lch);
            CP_COMMIT();
        }

        unsigned af[2][4], bf[4][4];
        unsigned abase = sm_u32(&Asm[s * STG_H + a_row * SROW + a_kb]);
        ldsm_x4(af[0], abase);
        ldsm_x4(af[1], abase + 16 * SROW * 2);
        unsigned bbase = sm_u32(&Bsm[s * STG_H + b_row * SROW + b_kb]);
#pragma unroll
        for (int bi = 0; bi < 4; bi++)
            ldsm_x4(bf[bi], bbase + bi * 16 * SROW * 2);

#pragma unroll
        for (int mf = 0; mf < 2; mf++)
#pragma unroll
            for (int nf = 0; nf < 8; nf++) {
                const int bi = nf >> 1, hi = (nf & 1) * 2;
                mma_fp16(acc[mf][nf], af[mf], bf[bi][hi], bf[bi][hi + 1]);
            }
    }

    // Epilogue (paired 64-bit stores; m pairs are contiguous: c*2, c*2+1)
#pragma unroll
    for (int mf = 0; mf < 2; mf++) {
#pragma unroll
        for (int r2 = 0; r2 < 2; r2++) {
            const int n = n0 + wr + mf * 16 + g + r2 * 8;
#pragma unroll
            for (int nf = 0; nf < 8; nf++) {
                const int m = m0 + wc + nf * 8 + c * 2;
                float v0 = acc[mf][nf][r2 * 2]     + bias[m];
                float v1 = acc[mf][nf][r2 * 2 + 1] + bias[m + 1];
                if (EPI == E_QKV) {
                    if (sel == 0) { v0 *= QSCALE; v1 *= QSCALE; }
                    const int t = n >> 2, b = n & 3, h = m >> 6, hd = m & 63;
                    *(half2*)&((__half*)C)[(((size_t)(b * H_DIM + h) * T_DIM) + t) * HD_DIM + hd] =
                        __floats2half2_rn(v0, v1);
                } else if (EPI == E_ADD_ALPHA) {
                    float2 ax = *(const float2*)&aux[(size_t)n * ldc + m];
                    float2 o; o.x = v0 + ax.x * ALPHA_C; o.y = v1 + ax.y * ALPHA_C;
                    *(float2*)&((float*)C)[(size_t)n * ldc + m] = o;
                } else { // E_GELU (exact) -> fp16
                    float g0 = 0.5f * v0 * (1.f + erff(v0 * 0.70710678118654752f));
                    float g1 = 0.5f * v1 * (1.f + erff(v1 * 0.70710678118654752f));
                    *(half2*)&((__half*)C)[(size_t)n * ldc + m] = __floats2half2_rn(g0, g1);
                }
            }
        }
    }
}

// ---------------------------------------------------------------------------
// Gate kernel (reads fp16 q)
// ---------------------------------------------------------------------------
__global__ void gate_kernel(const __half* __restrict__ q,
                            const float* __restrict__ grep_w,
                            const float* __restrict__ grep_b,
                            const float* __restrict__ grep_a,
                            float* __restrict__ gate)
{
    const int idx  = blockIdx.x * 8 + (threadIdx.x >> 5);
    const int lane = threadIdx.x & 31;
    const int d0 = lane, d1 = lane + 32;

    float wa0 = grep_w[d0] + grep_w[64 + d0] + grep_w[128 + d0] + grep_w[192 + d0];
    float wa1 = grep_w[d1] + grep_w[64 + d1] + grep_w[128 + d1] + grep_w[192 + d1];
    float wb0 = grep_w[256 + d0] + grep_w[320 + d0] + grep_w[384 + d0] + grep_w[448 + d0];
    float wb1 = grep_w[256 + d1] + grep_w[320 + d1] + grep_w[384 + d1] + grep_w[448 + d1];

    const __half* qr = q + (size_t)idx * 64;
    float q0 = __half2float(qr[d0]) * 256.f, q1 = __half2float(qr[d1]) * 256.f;
    float sa = q0 * wa0 + q1 * wa1;
    float sb = q0 * wb0 + q1 * wb1;
#pragma unroll
    for (int o = 16; o; o >>= 1) {
        sa += __shfl_xor_sync(0xffffffffu, sa, o);
        sb += __shfl_xor_sync(0xffffffffu, sb, o);
    }
    if (lane == 0) {
        sa += grep_b[0] + grep_b[1] + grep_b[2] + grep_b[3];
        sb += grep_b[4] + grep_b[5] + grep_b[6] + grep_b[7];
        float ga = 1.f / (1.f + __expf(-sa));
        float gb = 1.f / (1.f + __expf(-sb));
        int h = (idx >> 10) % H_DIM;
        gate[idx] = ga * (gb * grep_a[h] - 1.f) + 2.f;
    }
}

// ---------------------------------------------------------------------------
// Tensor-core flash attention + fused pb passthrough copy.
// Grid (8, 48): 128 q-rows/CTA, 8 warps x 16 rows. pb staged via cp.async.
// smem: Q 128x72h | K 2x64x72h | V 2x64x72h | PB 128x72f | gates 128f
// ---------------------------------------------------------------------------
#define FA_QH   (128 * 72)     // halves
#define FA_KVH  (64 * 72)      // halves per stage
#define FA_SMEM (FA_QH * 2 + 4 * FA_KVH * 2 + 128 * 72 * 4 + 512)

__global__ __launch_bounds__(256, 2) void flash_attn_h(
    const __half* __restrict__ q, const __half* __restrict__ k,
    const __half* __restrict__ v, const float* __restrict__ pb,
    const float* __restrict__ gate, __half* __restrict__ ctx,
    float* __restrict__ outpb)
{
    extern __shared__ __half smh[];
    __half* Qs  = smh;                        // 128x72 h
    __half* Ks  = smh + FA_QH;                // 2 stages 64x72 h
    __half* Vs  = smh + FA_QH + 2 * FA_KVH;   // 2 stages
    float*  PBs = (float*)(smh + FA_QH + 4 * FA_KVH);   // 128x72 f
    float*  Gs  = PBs + 128 * 72;

    const int bh   = blockIdx.y;
    const int q0   = blockIdx.x * 128;
    const int tid  = threadIdx.x;
    const int lane = tid & 31;
    const int w    = tid >> 5;
    const int g    = lane >> 2;
    const int c    = lane & 3;

    const __half* qg = q + ((size_t)bh * T_DIM + q0) * 64;
    const __half* kg = k + (size_t)bh * 65536;
    const __half* vg = v + (size_t)bh * 65536;
    const float*  pbg = pb + ((size_t)bh * T_DIM + q0) * T_DIM;

    // group 1: Q + K/V tile 0 + pb tile 0 ; group 2: K/V tile 1
#pragma unroll
    for (int i = tid; i < 1024; i += 256) {
        int row = i >> 3, ch = (i & 7) * 8;
        cp16(&Qs[row * 72 + ch], qg + row * 64 + ch);
    }
#pragma unroll
    for (int i = tid; i < 512; i += 256) {
        int row = i >> 3, ch = (i & 7) * 8;
        cp16(&Ks[row * 72 + ch], kg + row * 64 + ch);
        cp16(&Vs[row * 72 + ch], vg + row * 64 + ch);
    }
#pragma unroll
    for (int it = 0; it < 8; it++) {
        int cidx = tid + it * 256;            // 2048 16B chunks
        int row = cidx >> 4, chf = (cidx & 15) * 4;
        cp16(&PBs[row * 72 + chf], pbg + (size_t)row * T_DIM + chf);
    }
    CP_COMMIT();
#pragma unroll
    for (int i = tid; i < 512; i += 256) {
        int row = i >> 3, ch = (i & 7) * 8;
        cp16(&Ks[FA_KVH + row * 72 + ch], kg + 4096 + row * 64 + ch);
        cp16(&Vs[FA_KVH + row * 72 + ch], vg + 4096 + row * 64 + ch);
    }
    CP_COMMIT();
    if (tid < 128) Gs[tid] = gate[bh * T_DIM + q0 + tid];

    CP_WAIT(1);
    __syncthreads();

    // Q fragments (persist in registers)
    unsigned af[4][4];
    {
        const int ar  = w * 16 + (lane & 15);
        const int akb = (lane >> 4) * 8;
#pragma unroll
        for (int ks = 0; ks < 4; ks++)
            ldsm_x4(af[ks], sm_u32(&Qs[ar * 72 + ks * 16 + akb]));
    }

    float m0 = -1e30f, m1 = -1e30f, l0 = 0.f, l1 = 0.f;
    float oacc[8][4];
#pragma unroll
    for (int hb = 0; hb < 8; hb++)
#pragma unroll
        for (int j = 0; j < 4; j++) oacc[hb][j] = 0.f;

    const float gr0 = Gs[w * 16 + g];
    const float gr1 = Gs[w * 16 + g + 8];
    float* opb0 = outpb + ((size_t)bh * T_DIM + q0 + w * 16 + g) * T_DIM;
    float* opb1 = opb0 + 8 * T_DIM;

    const int brow = (lane & 7) + ((lane >> 4) & 1) * 8;
    const int bkb  = ((lane >> 3) & 1) * 8;
    const int vr   = lane & 15;
    const int vcb  = (lane >> 4) * 8;
    const int prow0 = (w * 16 + g) * 72;

    for (int t = 0; t < 16; t++) {
        const int buf = t & 1;
        // (1) KV(t) ready. outstanding allowed: P(t), K(t+1)  [t=15: P(15) only]
        if (t) {
            if (t < 15) CP_WAIT(2); else CP_WAIT(1);
            __syncthreads();
        }
        const __half* Kb = Ks + buf * FA_KVH;
        const __half* Vb = Vs + buf * FA_KVH;

        // (2) S = Q @ K^T  (this warp's 16 rows x 64 keys)
        float sacc[8][4];
#pragma unroll
        for (int nb = 0; nb < 8; nb++)
#pragma unroll
            for (int j = 0; j < 4; j++) sacc[nb][j] = 0.f;

#pragma unroll
        for (int nb2 = 0; nb2 < 4; nb2++) {
#pragma unroll
            for (int ks = 0; ks < 4; ks++) {
                unsigned bf[4];
                ldsm_x4(bf, sm_u32(&Kb[(nb2 * 16 + brow) * 72 + ks * 16 + bkb]));
                mma_fp16(sacc[nb2 * 2],     af[ks], bf[0], bf[1]);
                mma_fp16(sacc[nb2 * 2 + 1], af[ks], bf[2], bf[3]);
            }
        }

        // (3) pb(t) ready. outstanding allowed: K(t+1)  [t=15: none]
        if (t < 15) CP_WAIT(1); else CP_WAIT(0);
        __syncthreads();

        // (4) logits from smem pb + passthrough store + online softmax
        float mx0 = -1e30f, mx1 = -1e30f;
#pragma unroll
        for (int nb = 0; nb < 8; nb++) {
            float2 p0 = *(const float2*)&PBs[prow0 + nb * 8 + c * 2];
            float2 p1 = *(const float2*)&PBs[prow0 + 8 * 72 + nb * 8 + c * 2];
            *(float2*)&opb0[t * 64 + nb * 8 + c * 2] = p0;
            *(float2*)&opb1[t * 64 + nb * 8 + c * 2] = p1;
            sacc[nb][0] = 32.f * sacc[nb][0] + gr0 * p0.x;
            sacc[nb][1] = 32.f * sacc[nb][1] + gr0 * p0.y;
            sacc[nb][2] = 32.f * sacc[nb][2] + gr1 * p1.x;
            sacc[nb][3] = 32.f * sacc[nb][3] + gr1 * p1.y;
            mx0 = fmaxf(mx0, fmaxf(sacc[nb][0], sacc[nb][1]));
            mx1 = fmaxf(mx1, fmaxf(sacc[nb][2], sacc[nb][3]));
        }
        mx0 = fmaxf(mx0, __shfl_xor_sync(0xffffffffu, mx0, 1));
        mx0 = fmaxf(mx0, __shfl_xor_sync(0xffffffffu, mx0, 2));
        mx1 = fmaxf(mx1, __shfl_xor_sync(0xffffffffu, mx1, 1));
        mx1 = fmaxf(mx1, __shfl_xor_sync(0xffffffffu, mx1, 2));

        const float nm0 = fmaxf(m0, mx0), nm1 = fmaxf(m1, mx1);
        const float corr0 = __expf(m0 - nm0), corr1 = __expf(m1 - nm1);
        m0 = nm0; m1 = nm1;

        unsigned pa[4][4];
        float s0 = 0.f, s1 = 0.f;
#pragma unroll
        for (int nb = 0; nb < 8; nb++) {
            float e0 = __expf(sacc[nb][0] - nm0);
            float e1 = __expf(sacc[nb][1] - nm0);
            float e2 = __expf(sacc[nb][2] - nm1);
            float e3 = __expf(sacc[nb][3] - nm1);
            s0 += e0 + e1; s1 += e2 + e3;
            const int kp = nb >> 1, off = (nb & 1) * 2;
            half2 h0 = __floats2half2_rn(e0, e1);
            half2 h1 = __floats2half2_rn(e2, e3);
            pa[kp][off]     = *(unsigned*)&h0;
            pa[kp][off + 1] = *(unsigned*)&h1;
        }
        s0 += __shfl_xor_sync(0xffffffffu, s0, 1);
        s0 += __shfl_xor_sync(0xffffffffu, s0, 2);
        s1 += __shfl_xor_sync(0xffffffffu, s1, 1);
        s1 += __shfl_xor_sync(0xffffffffu, s1, 2);
        l0 = l0 * corr0 + s0;
        l1 = l1 * corr1 + s1;

#pragma unroll
        for (int hb = 0; hb < 8; hb++) {
            oacc[hb][0] *= corr0; oacc[hb][1] *= corr0;
            oacc[hb][2] *= corr1; oacc[hb][3] *= corr1;
        }

        // (5) all warps done reading PBs -> prefetch pb(t+1)
        __syncthreads();
        if (t + 1 < 16) {
#pragma unroll
            for (int it = 0; it < 8; it++) {
                int cidx = tid + it * 256;
                int row = cidx >> 4, chf = (cidx & 15) * 4;
                cp16(&PBs[row * 72 + chf],
                     pbg + (size_t)row * T_DIM + (t + 1) * 64 + chf);
            }
            CP_COMMIT();
        }

        // (6) out += P @ V   (V loaded transposed)
#pragma unroll
        for (int kp = 0; kp < 4; kp++) {
#pragma unroll
            for (int hb2 = 0; hb2 < 4; hb2++) {
                unsigned bv[4];
                ldsm_x4_t(bv, sm_u32(&Vb[(kp * 16 + vr) * 72 + hb2 * 16 + vcb]));
                mma_fp16(oacc[hb2 * 2],     pa[kp], bv[0], bv[1]);
                mma_fp16(oacc[hb2 * 2 + 1], pa[kp], bv[2], bv[3]);
            }
        }
        __syncthreads();   // all warps done reading KV buf

        // (7) prefetch K/V tile t+2 into the just-freed buffer
        if (t + 2 < 16) {
            const __half* ks2 = kg + (t + 2) * 4096;
            const __half* vs2 = vg + (t + 2) * 4096;
            __half* kd = Ks + buf * FA_KVH;
            __half* vd = Vs + buf * FA_KVH;
#pragma unroll
            for (int i = tid; i < 512; i += 256) {
                int row = i >> 3, ch = (i & 7) * 8;
                cp16(&kd[row * 72 + ch], ks2 + row * 64 + ch);
                cp16(&vd[row * 72 + ch], vs2 + row * 64 + ch);
            }
            CP_COMMIT();
        }
    }

    // write ctx (fp16, (T,B,D) layout) for Wo GEMM
    const float i0 = 1.f / l0, i1 = 1.f / l1;
    const int b = bh / H_DIM, hh = bh % H_DIM;
    const int t0g = q0 + w * 16 + g;
#pragma unroll
    for (int hb = 0; hb < 8; hb++) {
        const int col = hh * 64 + hb * 8 + c * 2;
        half2 o0 = __floats2half2_rn(oacc[hb][0] * i0, oacc[hb][1] * i0);
        half2 o1 = __floats2half2_rn(oacc[hb][2] * i1, oacc[hb][3] * i1);
        *(half2*)&ctx[(size_t)(t0g * B_DIM + b) * D_DIM + col]       = o0;
        *(half2*)&ctx[(size_t)((t0g + 8) * B_DIM + b) * D_DIM + col] = o1;
    }
}

// ---------------------------------------------------------------------------
// LayerNorm (optionally also emits fp16)
// ---------------------------------------------------------------------------
__global__ void layernorm_kernel(const float* __restrict__ in,
                                 const float* __restrict__ g,
                                 const float* __restrict__ b,
                                 float* __restrict__ out,
                                 __half* __restrict__ hout)
{
    const int row = blockIdx.x, tid = threadIdx.x;
    const float* xr = in + (size_t)row * D_DIM;
    float v0 = xr[tid], v1 = xr[tid + 256], v2 = xr[tid + 512];
    float s  = v0 + v1 + v2;
    float sq = v0 * v0 + v1 * v1 + v2 * v2;
#pragma unroll
    for (int o = 16; o; o >>= 1) {
        s  += __shfl_xor_sync(0xffffffffu, s,  o);
        sq += __shfl_xor_sync(0xffffffffu, sq, o);
    }
    __shared__ float ss[8], sqs[8], stats[2];
    const int w = tid >> 5, lane = tid & 31;
    if (lane == 0) { ss[w] = s; sqs[w] = sq; }
    __syncthreads();
    if (tid == 0) {
        float S = 0.f, SQ = 0.f;
        for (int i = 0; i < 8; i++) { S += ss[i]; SQ += sqs[i]; }
        float mu  = S * (1.f / 768.f);
        float var = SQ * (1.f / 768.f) - mu * mu;
        stats[0] = mu;
        stats[1] = rsqrtf(var + 1e-5f);
    }
    __syncthreads();
    const float mu = stats[0], rstd = stats[1];
    float r0 = (v0 - mu) * rstd * g[tid]       + b[tid];
    float r1 = (v1 - mu) * rstd * g[tid + 256] + b[tid + 256];
    float r2 = (v2 - mu) * rstd * g[tid + 512] + b[tid + 512];
    float* orow = out + (size_t)row * D_DIM;
    orow[tid] = r0; orow[tid + 256] = r1; orow[tid + 512] = r2;
    if (hout) {
        __half* hrow = hout + (size_t)row * D_DIM;
        hrow[tid] = __float2half_rn(r0);
        hrow[tid + 256] = __float2half_rn(r1);
        hrow[tid + 512] = __float2half_rn(r2);
    }
}

// ---------------------------------------------------------------------------
// Launch
// ---------------------------------------------------------------------------
extern "C" void kernel_launch(void* const* d_in, const int* in_sizes, int n_in,
                              void* d_out, int out_size)
{
    const float* states = (const float*)d_in[0];
    const float* pb     = (const float*)d_in[1];
    const float* Wq = (const float*)d_in[2];   const float* bq = (const float*)d_in[3];
    const float* Wk = (const float*)d_in[4];   const float* bk = (const float*)d_in[5];
    const float* Wv = (const float*)d_in[6];   const float* bv = (const float*)d_in[7];
    const float* Wo = (const float*)d_in[8];   const float* bo = (const float*)d_in[9];
    const float* grep_w = (const float*)d_in[10];
    const float* grep_b = (const float*)d_in[11];
    const float* grep_a = (const float*)d_in[12];
    const float* ln1_g  = (const float*)d_in[13];
    const float* ln1_b  = (const float*)d_in[14];
    const float* W1 = (const float*)d_in[15];  const float* b1 = (const float*)d_in[16];
    const float* W2 = (const float*)d_in[17];  const float* b2 = (const float*)d_in[18];
    const float* ln2_g  = (const float*)d_in[19];
    const float* ln2_b  = (const float*)d_in[20];
    float* out = (float*)d_out;

    __half *hstates, *hWq, *hWk, *hWv, *hWo, *hW1, *hW2;
    __half *hq, *hk, *hv, *hctx, *hx, *hh;
    float  *gate, *y1, *x, *y2;
    cudaGetSymbolAddress((void**)&hstates, g_hstates);
    cudaGetSymbolAddress((void**)&hWq, g_hWq);
    cudaGetSymbolAddress((void**)&hWk, g_hWk);
    cudaGetSymbolAddress((void**)&hWv, g_hWv);
    cudaGetSymbolAddress((void**)&hWo, g_hWo);
    cudaGetSymbolAddress((void**)&hW1, g_hW1);
    cudaGetSymbolAddress((void**)&hW2, g_hW2);
    cudaGetSymbolAddress((void**)&hq,  g_hq);
    cudaGetSymbolAddress((void**)&hk,  g_hk);
    cudaGetSymbolAddress((void**)&hv,  g_hv);
    cudaGetSymbolAddress((void**)&hctx, g_hctx);
    cudaGetSymbolAddress((void**)&hx,  g_hx);
    cudaGetSymbolAddress((void**)&hh,  g_hh);
    cudaGetSymbolAddress((void**)&gate, g_gate);
    cudaGetSymbolAddress((void**)&y1,  g_y1);
    cudaGetSymbolAddress((void**)&x,   g_x);
    cudaGetSymbolAddress((void**)&y2,  g_y2);

    cudaFuncSetAttribute(mm_h<E_QKV>,      cudaFuncAttributeMaxDynamicSharedMemorySize, MM_SMEM);
    cudaFuncSetAttribute(mm_h<E_ADD_ALPHA>,cudaFuncAttributeMaxDynamicSharedMemorySize, MM_SMEM);
    cudaFuncSetAttribute(mm_h<E_GELU>,     cudaFuncAttributeMaxDynamicSharedMemorySize, MM_SMEM);
    cudaFuncSetAttribute(flash_attn_h,     cudaFuncAttributeMaxDynamicSharedMemorySize, FA_SMEM);

    const dim3 blk(256);

    // fp32 -> fp16 for states + weights
    f2h_all<<<2496, blk>>>(states, Wq, Wk, Wv, Wo, W1, W2);

    // Fused QKV projections (fp16 tensor cores, scattered to head-major fp16)
    mm_h<E_QKV><<<dim3(18, 32), blk, MM_SMEM>>>(
        hstates, hWq, hWk, hWv, bq, bk, bv, nullptr, hq, hk, hv, D_DIM, 0);

    // gating
    gate_kernel<<<NHEADS * T_DIM / 8, blk>>>(hq, grep_w, grep_b, grep_a, gate);

    // tensor-core flash attention (+ fused pb passthrough into out)
    flash_attn_h<<<dim3(T_DIM / 128, NHEADS), blk, FA_SMEM>>>(
        hq, hk, hv, pb, gate, hctx, out + (size_t)NROWS * D_DIM);

    // Wo projection + residual (fp32 aux), then LN1 (fp32 + fp16 out)
    mm_h<E_ADD_ALPHA><<<dim3(6, 32), blk, MM_SMEM>>>(
        hctx, hWo, nullptr, nullptr, bo, nullptr, nullptr,
        states, y1, nullptr, nullptr, D_DIM, D_DIM);
    layernorm_kernel<<<NROWS, blk>>>(y1, ln1_g, ln1_b, x, hx);

    // FFN
    mm_h<E_GELU><<<dim3(24, 32), blk, MM_SMEM>>>(
        hx, hW1, nullptr, nullptr, b1, nullptr, nullptr,
        nullptr, hh, nullptr, nullptr, D_DIM, FF_DIM);
    mm_h<E_ADD_ALPHA><<<dim3(6, 32), blk, MM_SMEM>>>(
        hh, hW2, nullptr, nullptr, b2, nullptr, nullptr,
        x, y2, nullptr, nullptr, FF_DIM, D_DIM);
    layernorm_kernel<<<NROWS, blk>>>(y2, ln2_g, ln2_b, out, nullptr);
}

// round 9
// speedup vs baseline: 5.5132x; 1.0314x over previous
#include <cuda_runtime.h>
#include <cuda_fp16.h>
#include <math.h>

// ---------------------------------------------------------------------------
// Problem constants
// ---------------------------------------------------------------------------
#define T_DIM   1024
#define B_DIM   4
#define D_DIM   768
#define H_DIM   12
#define HD_DIM  64
#define FF_DIM  3072
#define NROWS   4096          // T*B
#define NHEADS  48            // B*H
#define ALPHA_C 2.2133638394006434f   // 24^0.25
#define QSCALE  0.00390625f           // 0.125/32

// ---------------------------------------------------------------------------
// Scratch (device globals: allocation-free rule)
// ---------------------------------------------------------------------------
__device__ __half g_hstates[NROWS * D_DIM];
__device__ __half g_hWq[D_DIM * D_DIM];
__device__ __half g_hWk[D_DIM * D_DIM];
__device__ __half g_hWv[D_DIM * D_DIM];
__device__ __half g_hWo[D_DIM * D_DIM];
__device__ __half g_hW1[FF_DIM * D_DIM];
__device__ __half g_hW2[D_DIM * FF_DIM];
__device__ __half g_hq [NHEADS * T_DIM * HD_DIM];
__device__ __half g_hk [NHEADS * T_DIM * HD_DIM];
__device__ __half g_hv [NHEADS * T_DIM * HD_DIM];
__device__ __half g_hctx[NROWS * D_DIM];
__device__ __half g_hx [NROWS * D_DIM];
__device__ __half g_hh [NROWS * FF_DIM];
__device__ float  g_gate[NHEADS * T_DIM];
__device__ float  g_y1 [NROWS * D_DIM];
__device__ float  g_x  [NROWS * D_DIM];
__device__ float  g_y2 [NROWS * D_DIM];

// ---------------------------------------------------------------------------
// PTX helpers
// ---------------------------------------------------------------------------
__device__ __forceinline__ unsigned sm_u32(const void* p) {
    return (unsigned)__cvta_generic_to_shared(p);
}
__device__ __forceinline__ void cp16(void* s, const void* g) {
    asm volatile("cp.async.ca.shared.global [%0], [%1], 16;\n"
                 :: "r"(sm_u32(s)), "l"(g));
}
#define CP_COMMIT() asm volatile("cp.async.commit_group;\n")
#define CP_WAIT(N)  asm volatile("cp.async.wait_group %0;\n" :: "n"(N))

__device__ __forceinline__ void ldsm_x4(unsigned* f, unsigned addr) {
    asm volatile("ldmatrix.sync.aligned.m8n8.x4.shared.b16 {%0,%1,%2,%3}, [%4];"
                 : "=r"(f[0]), "=r"(f[1]), "=r"(f[2]), "=r"(f[3]) : "r"(addr));
}
__device__ __forceinline__ void ldsm_x4_t(unsigned* f, unsigned addr) {
    asm volatile("ldmatrix.sync.aligned.m8n8.x4.trans.shared.b16 {%0,%1,%2,%3}, [%4];"
                 : "=r"(f[0]), "=r"(f[1]), "=r"(f[2]), "=r"(f[3]) : "r"(addr));
}
__device__ __forceinline__ void mma_fp16(float* d, const unsigned* a,
                                         unsigned b0, unsigned b1) {
    asm volatile(
        "mma.sync.aligned.m16n8k16.row.col.f32.f16.f16.f32 "
        "{%0,%1,%2,%3}, {%4,%5,%6,%7}, {%8,%9}, {%0,%1,%2,%3};\n"
        : "+f"(d[0]), "+f"(d[1]), "+f"(d[2]), "+f"(d[3])
        : "r"(a[0]), "r"(a[1]), "r"(a[2]), "r"(a[3]), "r"(b0), "r"(b1));
}

// ---------------------------------------------------------------------------
// fp32 -> fp16 conversion of states + all 6 weight matrices (one launch)
// ---------------------------------------------------------------------------
__global__ void f2h_all(const float* __restrict__ s0, const float* __restrict__ wq,
                        const float* __restrict__ wk, const float* __restrict__ wv,
                        const float* __restrict__ wo, const float* __restrict__ w1,
                        const float* __restrict__ w2)
{
    const int total4 = 2555904;  // 10,223,616 floats / 4
    for (int i = blockIdx.x * blockDim.x + threadIdx.x; i < total4;
         i += gridDim.x * blockDim.x) {
        int f = i * 4;
        const float* src; __half* dst; int off;
        if      (f < 3145728) { src = s0; dst = g_hstates; off = f; }
        else if (f < 3735552) { src = wq; dst = g_hWq; off = f - 3145728; }
        else if (f < 4325376) { src = wk; dst = g_hWk; off = f - 3735552; }
        else if (f < 4915200) { src = wv; dst = g_hWv; off = f - 4325376; }
        else if (f < 5505024) { src = wo; dst = g_hWo; off = f - 4915200; }
        else if (f < 7864320) { src = w1; dst = g_hW1; off = f - 5505024; }
        else                  { src = w2; dst = g_hW2; off = f - 7864320; }
        float4 v = *(const float4*)(src + off);
        half2* d = (half2*)(dst + off);
        d[0] = __floats2half2_rn(v.x, v.y);
        d[1] = __floats2half2_rn(v.z, v.w);
    }
}

// ---------------------------------------------------------------------------
// fp16 tensor-core GEMM with 5-stage cp.async pipeline (1 barrier / k-iter).
// C = A(N x K) @ W(M x K)^T  (+ fused epilogue)
// E_QKV additionally computes the gating values from the raw Q outputs
// (scale 0.125/32 * 256 cancels; q_full = raw + bias).
// ---------------------------------------------------------------------------
enum { E_QKV = 0, E_ADD_ALPHA = 1, E_GELU = 2 };

#define SROW   24        // halves per smem row (16 data + 8 pad)
#define STAGES 5
#define STG_H  (128 * SROW)                      // halves per operand per stage
#define MM_SMEM (2 * STAGES * STG_H * 2 + 512)   // bytes (+ wsum buffer)

template <int EPI>
__global__ __launch_bounds__(256, 2) void mm_h(
    const __half* __restrict__ A,
    const __half* __restrict__ W0, const __half* __restrict__ W1h, const __half* __restrict__ W2h,
    const float* __restrict__ bp0, const float* __restrict__ bp1, const float* __restrict__ bp2,
    const float* __restrict__ aux,
    void* __restrict__ C0, void* __restrict__ C1, void* __restrict__ C2,
    const float* __restrict__ gw, const float* __restrict__ gbb,
    const float* __restrict__ gai, float* __restrict__ gate_out,
    int K, int ldc)
{
    extern __shared__ __half smh[];
    __half* Asm = smh;                     // STAGES * STG_H
    __half* Bsm = smh + STAGES * STG_H;
    float*  wsum = (float*)(smh + 2 * STAGES * STG_H);   // 128 floats

    int sel = 0, mblk = blockIdx.x;
    const __half* W = W0; const float* bias = bp0; void* C = C0;
    if (EPI == E_QKV) {
        sel  = blockIdx.x / 6;
        mblk = blockIdx.x % 6;
        if (sel == 1) { W = W1h; bias = bp1; C = C1; }
        else if (sel == 2) { W = W2h; bias = bp2; C = C2; }
    }

    const int n0 = blockIdx.y * 128;
    const int m0 = mblk * 128;
    const int tid  = threadIdx.x;
    const int lane = tid & 31;
    const int wid  = tid >> 5;
    const int wr = (wid >> 1) * 32;
    const int wc = (wid & 1)  * 64;
    const int g = lane >> 2;
    const int c = lane & 3;

    // stage summed grep_w rows (gate path) — visible after first mainloop barrier
    if (EPI == E_QKV && sel == 0 && tid < 128) {
        const int hd = tid & 63, base = (tid >> 6) * 256;
        wsum[tid] = gw[base + hd] + gw[base + 64 + hd]
                  + gw[base + 128 + hd] + gw[base + 192 + hd];
    }

    float acc[2][8][4];
#pragma unroll
    for (int mf = 0; mf < 2; mf++)
#pragma unroll
        for (int nf = 0; nf < 8; nf++)
#pragma unroll
            for (int r = 0; r < 4; r++) acc[mf][nf][r] = 0.f;

    const __half* Ab = A + (size_t)n0 * K;
    const __half* Wb = W + (size_t)m0 * K;

    const int lrow = tid >> 1;         // 0..127
    const int lch  = (tid & 1) * 8;    // halves: 0 or 8

    const int NK = K >> 4;

    // prologue: stages 0..3
#pragma unroll
    for (int s = 0; s < 4; s++) {
        cp16(&Asm[s * STG_H + lrow * SROW + lch], Ab + (size_t)lrow * K + s * 16 + lch);
        cp16(&Bsm[s * STG_H + lrow * SROW + lch], Wb + (size_t)lrow * K + s * 16 + lch);
        CP_COMMIT();
    }

    const int a_row = wr + (lane & 15);
    const int a_kb  = (lane >> 4) * 8;
    const int b_row = wc + (lane & 7) + ((lane >> 4) & 1) * 8;
    const int b_kb  = ((lane >> 3) & 1) * 8;

    for (int i = 0; i < NK; i++) {
        const int s   = i % STAGES;
        const int rem = NK - i - 1;
        if      (rem >= 3) CP_WAIT(3);
        else if (rem == 2) CP_WAIT(2);
        else if (rem == 1) CP_WAIT(1);
        else               CP_WAIT(0);
        __syncthreads();

        if (i + 4 < NK) {
            const int s2 = (i + 4) % STAGES;
            const int kt = (i + 4) * 16;
            cp16(&Asm[s2 * STG_H + lrow * SROW + lch], Ab + (size_t)lrow * K + kt + lch);
            cp16(&Bsm[s2 * STG_H + lrow * SROW + lch], Wb + (size_t)lrow * K + kt + lch);
            CP_COMMIT();
        }

        unsigned af[2][4], bf[4][4];
        unsigned abase = sm_u32(&Asm[s * STG_H + a_row * SROW + a_kb]);
        ldsm_x4(af[0], abase);
        ldsm_x4(af[1], abase + 16 * SROW * 2);
        unsigned bbase = sm_u32(&Bsm[s * STG_H + b_row * SROW + b_kb]);
#pragma unroll
        for (int bi = 0; bi < 4; bi++)
            ldsm_x4(bf[bi], bbase + bi * 16 * SROW * 2);

#pragma unroll
        for (int mf = 0; mf < 2; mf++)
#pragma unroll
            for (int nf = 0; nf < 8; nf++) {
                const int bi = nf >> 1, hi = (nf & 1) * 2;
                mma_fp16(acc[mf][nf], af[mf], bf[bi][hi], bf[bi][hi + 1]);
            }
    }

    // gate-path per-thread weights (16 cols this thread owns)
    float was[16], wbs[16], bsum_a = 0.f, bsum_b = 0.f, gah = 0.f;
    if (EPI == E_QKV && sel == 0) {
#pragma unroll
        for (int nf = 0; nf < 8; nf++) {
            const int hd = (wc + nf * 8 + c * 2) & 63;
            was[nf * 2]     = wsum[hd];
            was[nf * 2 + 1] = wsum[hd + 1];      // hd even, +1 stays in-range
            wbs[nf * 2]     = wsum[64 + hd];
            wbs[nf * 2 + 1] = wsum[64 + hd + 1];
        }
        bsum_a = gbb[0] + gbb[1] + gbb[2] + gbb[3];
        bsum_b = gbb[4] + gbb[5] + gbb[6] + gbb[7];
        gah = gai[(m0 + wc) >> 6];
    }

    // Epilogue (paired 64-bit stores)
#pragma unroll
    for (int mf = 0; mf < 2; mf++) {
#pragma unroll
        for (int r2 = 0; r2 < 2; r2++) {
            const int n = n0 + wr + mf * 16 + g + r2 * 8;
            float sa = 0.f, sb = 0.f;
#pragma unroll
            for (int nf = 0; nf < 8; nf++) {
                const int m = m0 + wc + nf * 8 + c * 2;
                float v0 = acc[mf][nf][r2 * 2]     + bias[m];
                float v1 = acc[mf][nf][r2 * 2 + 1] + bias[m + 1];
                if (EPI == E_QKV) {
                    if (sel == 0) {
                        sa += v0 * was[nf * 2] + v1 * was[nf * 2 + 1];
                        sb += v0 * wbs[nf * 2] + v1 * wbs[nf * 2 + 1];
                        v0 *= QSCALE; v1 *= QSCALE;
                    }
                    const int t = n >> 2, b = n & 3, h = m >> 6, hd = m & 63;
                    *(half2*)&((__half*)C)[(((size_t)(b * H_DIM + h) * T_DIM) + t) * HD_DIM + hd] =
                        __floats2half2_rn(v0, v1);
                } else if (EPI == E_ADD_ALPHA) {
                    float2 ax = *(const float2*)&aux[(size_t)n * ldc + m];
                    float2 o; o.x = v0 + ax.x * ALPHA_C; o.y = v1 + ax.y * ALPHA_C;
                    *(float2*)&((float*)C)[(size_t)n * ldc + m] = o;
                } else { // E_GELU (exact) -> fp16
                    float g0 = 0.5f * v0 * (1.f + erff(v0 * 0.70710678118654752f));
                    float g1 = 0.5f * v1 * (1.f + erff(v1 * 0.70710678118654752f));
                    *(half2*)&((__half*)C)[(size_t)n * ldc + m] = __floats2half2_rn(g0, g1);
                }
            }
            if (EPI == E_QKV && sel == 0) {
                sa += __shfl_xor_sync(0xffffffffu, sa, 1);
                sa += __shfl_xor_sync(0xffffffffu, sa, 2);
                sb += __shfl_xor_sync(0xffffffffu, sb, 1);
                sb += __shfl_xor_sync(0xffffffffu, sb, 2);
                if (c == 0) {
                    float ga = 1.f / (1.f + __expf(-(sa + bsum_a)));
                    float gb = 1.f / (1.f + __expf(-(sb + bsum_b)));
                    const int t = n >> 2, b = n & 3, h = (m0 + wc) >> 6;
                    gate_out[(b * H_DIM + h) * T_DIM + t] = ga * (gb * gah - 1.f) + 2.f;
                }
            }
        }
    }
}

// ---------------------------------------------------------------------------
// Tensor-core flash attention + fused pb passthrough copy.
// Grid (8, 48): 128 q-rows/CTA, 8 warps x 16 rows.
// pb staged per-warp (each warp owns its 16 rows) -> only 2 block barriers/tile.
// smem: Q 128x72h | K 2x64x72h | V 2x64x72h | PB 128x72f | gates 128f
// ---------------------------------------------------------------------------
#define FA_QH   (128 * 72)     // halves
#define FA_KVH  (64 * 72)      // halves per stage
#define FA_SMEM (FA_QH * 2 + 4 * FA_KVH * 2 + 128 * 72 * 4 + 512)

__global__ __launch_bounds__(256, 2) void flash_attn_h(
    const __half* __restrict__ q, const __half* __restrict__ k,
    const __half* __restrict__ v, const float* __restrict__ pb,
    const float* __restrict__ gate, __half* __restrict__ ctx,
    float* __restrict__ outpb)
{
    extern __shared__ __half smh[];
    __half* Qs  = smh;                        // 128x72 h
    __half* Ks  = smh + FA_QH;                // 2 stages 64x72 h
    __half* Vs  = smh + FA_QH + 2 * FA_KVH;   // 2 stages
    float*  PBs = (float*)(smh + FA_QH + 4 * FA_KVH);   // 128x72 f
    float*  Gs  = PBs + 128 * 72;

    const int bh   = blockIdx.y;
    const int q0   = blockIdx.x * 128;
    const int tid  = threadIdx.x;
    const int lane = tid & 31;
    const int w    = tid >> 5;
    const int g    = lane >> 2;
    const int c    = lane & 3;

    const __half* qg = q + ((size_t)bh * T_DIM + q0) * 64;
    const __half* kg = k + (size_t)bh * 65536;
    const __half* vg = v + (size_t)bh * 65536;
    const float*  pbg = pb + ((size_t)bh * T_DIM + q0) * T_DIM;

    // group 1: Q + K/V tile 0 + pb tile 0 (warp-local rows) ; group 2: K/V tile 1
#pragma unroll
    for (int i = tid; i < 1024; i += 256) {
        int row = i >> 3, ch = (i & 7) * 8;
        cp16(&Qs[row * 72 + ch], qg + row * 64 + ch);
    }
#pragma unroll
    for (int i = tid; i < 512; i += 256) {
        int row = i >> 3, ch = (i & 7) * 8;
        cp16(&Ks[row * 72 + ch], kg + row * 64 + ch);
        cp16(&Vs[row * 72 + ch], vg + row * 64 + ch);
    }
#pragma unroll
    for (int it = 0; it < 8; it++) {
        int cidx = lane + it * 32;               // 256 chunks per warp
        int row  = w * 16 + (cidx >> 4);
        int chf  = (cidx & 15) * 4;
        cp16(&PBs[row * 72 + chf], pbg + (size_t)row * T_DIM + chf);
    }
    CP_COMMIT();
#pragma unroll
    for (int i = tid; i < 512; i += 256) {
        int row = i >> 3, ch = (i & 7) * 8;
        cp16(&Ks[FA_KVH + row * 72 + ch], kg + 4096 + row * 64 + ch);
        cp16(&Vs[FA_KVH + row * 72 + ch], vg + 4096 + row * 64 + ch);
    }
    CP_COMMIT();
    if (tid < 128) Gs[tid] = gate[bh * T_DIM + q0 + tid];

    CP_WAIT(1);
    __syncthreads();

    // Q fragments (persist in registers)
    unsigned af[4][4];
    {
        const int ar  = w * 16 + (lane & 15);
        const int akb = (lane >> 4) * 8;
#pragma unroll
        for (int ks = 0; ks < 4; ks++)
            ldsm_x4(af[ks], sm_u32(&Qs[ar * 72 + ks * 16 + akb]));
    }

    float m0 = -1e30f, m1 = -1e30f, l0 = 0.f, l1 = 0.f;
    float oacc[8][4];
#pragma unroll
    for (int hb = 0; hb < 8; hb++)
#pragma unroll
        for (int j = 0; j < 4; j++) oacc[hb][j] = 0.f;

    const float gr0 = Gs[w * 16 + g];
    const float gr1 = Gs[w * 16 + g + 8];
    float* opb0 = outpb + ((size_t)bh * T_DIM + q0 + w * 16 + g) * T_DIM;
    float* opb1 = opb0 + 8 * T_DIM;

    const int brow = (lane & 7) + ((lane >> 4) & 1) * 8;
    const int bkb  = ((lane >> 3) & 1) * 8;
    const int vr   = lane & 15;
    const int vcb  = (lane >> 4) * 8;
    const int prow0 = (w * 16 + g) * 72;

    for (int t = 0; t < 16; t++) {
        const int buf = t & 1;
        // (1) KV(t) ready. outstanding allowed: PB(t), KV(t+1)  [t=15: PB(15) only]
        if (t) {
            if (t < 15) CP_WAIT(2); else CP_WAIT(1);
            __syncthreads();
        }
        const __half* Kb = Ks + buf * FA_KVH;
        const __half* Vb = Vs + buf * FA_KVH;

        // (2) S = Q @ K^T  (this warp's 16 rows x 64 keys)
        float sacc[8][4];
#pragma unroll
        for (int nb = 0; nb < 8; nb++)
#pragma unroll
            for (int j = 0; j < 4; j++) sacc[nb][j] = 0.f;

#pragma unroll
        for (int nb2 = 0; nb2 < 4; nb2++) {
#pragma unroll
            for (int ks = 0; ks < 4; ks++) {
                unsigned bf[4];
                ldsm_x4(bf, sm_u32(&Kb[(nb2 * 16 + brow) * 72 + ks * 16 + bkb]));
                mma_fp16(sacc[nb2 * 2],     af[ks], bf[0], bf[1]);
                mma_fp16(sacc[nb2 * 2 + 1], af[ks], bf[2], bf[3]);
            }
        }

        // (3) PB(t) ready (warp-local). outstanding allowed: KV(t+1) [t=15: none]
        if (t < 15) CP_WAIT(1); else CP_WAIT(0);
        __syncwarp();

        // (4) logits from smem pb + passthrough store + online softmax
        float mx0 = -1e30f, mx1 = -1e30f;
#pragma unroll
        for (int nb = 0; nb < 8; nb++) {
            float2 p0 = *(const float2*)&PBs[prow0 + nb * 8 + c * 2];
            float2 p1 = *(const float2*)&PBs[prow0 + 8 * 72 + nb * 8 + c * 2];
            *(float2*)&opb0[t * 64 + nb * 8 + c * 2] = p0;
            *(float2*)&opb1[t * 64 + nb * 8 + c * 2] = p1;
            sacc[nb][0] = 32.f * sacc[nb][0] + gr0 * p0.x;
            sacc[nb][1] = 32.f * sacc[nb][1] + gr0 * p0.y;
            sacc[nb][2] = 32.f * sacc[nb][2] + gr1 * p1.x;
            sacc[nb][3] = 32.f * sacc[nb][3] + gr1 * p1.y;
            mx0 = fmaxf(mx0, fmaxf(sacc[nb][0], sacc[nb][1]));
            mx1 = fmaxf(mx1, fmaxf(sacc[nb][2], sacc[nb][3]));
        }
        mx0 = fmaxf(mx0, __shfl_xor_sync(0xffffffffu, mx0, 1));
        mx0 = fmaxf(mx0, __shfl_xor_sync(0xffffffffu, mx0, 2));
        mx1 = fmaxf(mx1, __shfl_xor_sync(0xffffffffu, mx1, 1));
        mx1 = fmaxf(mx1, __shfl_xor_sync(0xffffffffu, mx1, 2));

        const float nm0 = fmaxf(m0, mx0), nm1 = fmaxf(m1, mx1);
        const float corr0 = __expf(m0 - nm0), corr1 = __expf(m1 - nm1);
        m0 = nm0; m1 = nm1;

        unsigned pa[4][4];
        float s0 = 0.f, s1 = 0.f;
#pragma unroll
        for (int nb = 0; nb < 8; nb++) {
            float e0 = __expf(sacc[nb][0] - nm0);
            float e1 = __expf(sacc[nb][1] - nm0);
            float e2 = __expf(sacc[nb][2] - nm1);
            float e3 = __expf(sacc[nb][3] - nm1);
            s0 += e0 + e1; s1 += e2 + e3;
            const int kp = nb >> 1, off = (nb & 1) * 2;
            half2 h0 = __floats2half2_rn(e0, e1);
            half2 h1 = __floats2half2_rn(e2, e3);
            pa[kp][off]     = *(unsigned*)&h0;
            pa[kp][off + 1] = *(unsigned*)&h1;
        }
        s0 += __shfl_xor_sync(0xffffffffu, s0, 1);
        s0 += __shfl_xor_sync(0xffffffffu, s0, 2);
        s1 += __shfl_xor_sync(0xffffffffu, s1, 1);
        s1 += __shfl_xor_sync(0xffffffffu, s1, 2);
        l0 = l0 * corr0 + s0;
        l1 = l1 * corr1 + s1;

#pragma unroll
        for (int hb = 0; hb < 8; hb++) {
            oacc[hb][0] *= corr0; oacc[hb][1] *= corr0;
            oacc[hb][2] *= corr1; oacc[hb][3] *= corr1;
        }

        // (5) warp done reading its PB rows -> warp-local prefetch of pb(t+1)
        __syncwarp();
        if (t + 1 < 16) {
#pragma unroll
            for (int it = 0; it < 8; it++) {
                int cidx = lane + it * 32;
                int row  = w * 16 + (cidx >> 4);
                int chf  = (cidx & 15) * 4;
                cp16(&PBs[row * 72 + chf],
                     pbg + (size_t)row * T_DIM + (t + 1) * 64 + chf);
            }
            CP_COMMIT();
        }

        // (6) out += P @ V   (V loaded transposed)
#pragma unroll
        for (int kp = 0; kp < 4; kp++) {
#pragma unroll
            for (int hb2 = 0; hb2 < 4; hb2++) {
                unsigned bv[4];
                ldsm_x4_t(bv, sm_u32(&Vb[(kp * 16 + vr) * 72 + hb2 * 16 + vcb]));
                mma_fp16(oacc[hb2 * 2],     pa[kp], bv[0], bv[1]);
                mma_fp16(oacc[hb2 * 2 + 1], pa[kp], bv[2], bv[3]);
            }
        }
        __syncthreads();   // all warps done reading KV buf

        // (7) prefetch K/V tile t+2 into the just-freed buffer
        if (t + 2 < 16) {
            const __half* ks2 = kg + (t + 2) * 4096;
            const __half* vs2 = vg + (t + 2) * 4096;
            __half* kd = Ks + buf * FA_KVH;
            __half* vd = Vs + buf * FA_KVH;
#pragma unroll
            for (int i = tid; i < 512; i += 256) {
                int row = i >> 3, ch = (i & 7) * 8;
                cp16(&kd[row * 72 + ch], ks2 + row * 64 + ch);
                cp16(&vd[row * 72 + ch], vs2 + row * 64 + ch);
            }
            CP_COMMIT();
        }
    }

    // write ctx (fp16, (T,B,D) layout) for Wo GEMM
    const float i0 = 1.f / l0, i1 = 1.f / l1;
    const int b = bh / H_DIM, hh = bh % H_DIM;
    const int t0g = q0 + w * 16 + g;
#pragma unroll
    for (int hb = 0; hb < 8; hb++) {
        const int col = hh * 64 + hb * 8 + c * 2;
        half2 o0 = __floats2half2_rn(oacc[hb][0] * i0, oacc[hb][1] * i0);
        half2 o1 = __floats2half2_rn(oacc[hb][2] * i1, oacc[hb][3] * i1);
        *(half2*)&ctx[(size_t)(t0g * B_DIM + b) * D_DIM + col]       = o0;
        *(half2*)&ctx[(size_t)((t0g + 8) * B_DIM + b) * D_DIM + col] = o1;
    }
}

// ---------------------------------------------------------------------------
// LayerNorm (optionally also emits fp16)
// ---------------------------------------------------------------------------
__global__ void layernorm_kernel(const float* __restrict__ in,
                                 const float* __restrict__ g,
                                 const float* __restrict__ b,
                                 float* __restrict__ out,
                                 __half* __restrict__ hout)
{
    const int row = blockIdx.x, tid = threadIdx.x;
    const float* xr = in + (size_t)row * D_DIM;
    float v0 = xr[tid], v1 = xr[tid + 256], v2 = xr[tid + 512];
    float s  = v0 + v1 + v2;
    float sq = v0 * v0 + v1 * v1 + v2 * v2;
#pragma unroll
    for (int o = 16; o; o >>= 1) {
        s  += __shfl_xor_sync(0xffffffffu, s,  o);
        sq += __shfl_xor_sync(0xffffffffu, sq, o);
    }
    __shared__ float ss[8], sqs[8], stats[2];
    const int w = tid >> 5, lane = tid & 31;
    if (lane == 0) { ss[w] = s; sqs[w] = sq; }
    __syncthreads();
    if (tid == 0) {
        float S = 0.f, SQ = 0.f;
        for (int i = 0; i < 8; i++) { S += ss[i]; SQ += sqs[i]; }
        float mu  = S * (1.f / 768.f);
        float var = SQ * (1.f / 768.f) - mu * mu;
        stats[0] = mu;
        stats[1] = rsqrtf(var + 1e-5f);
    }
    __syncthreads();
    const float mu = stats[0], rstd = stats[1];
    float r0 = (v0 - mu) * rstd * g[tid]       + b[tid];
    float r1 = (v1 - mu) * rstd * g[tid + 256] + b[tid + 256];
    float r2 = (v2 - mu) * rstd * g[tid + 512] + b[tid + 512];
    float* orow = out + (size_t)row * D_DIM;
    orow[tid] = r0; orow[tid + 256] = r1; orow[tid + 512] = r2;
    if (hout) {
        __half* hrow = hout + (size_t)row * D_DIM;
        hrow[tid] = __float2half_rn(r0);
        hrow[tid + 256] = __float2half_rn(r1);
        hrow[tid + 512] = __float2half_rn(r2);
    }
}

// ---------------------------------------------------------------------------
// Launch
// ---------------------------------------------------------------------------
extern "C" void kernel_launch(void* const* d_in, const int* in_sizes, int n_in,
                              void* d_out, int out_size)
{
    const float* states = (const float*)d_in[0];
    const float* pb     = (const float*)d_in[1];
    const float* Wq = (const float*)d_in[2];   const float* bq = (const float*)d_in[3];
    const float* Wk = (const float*)d_in[4];   const float* bk = (const float*)d_in[5];
    const float* Wv = (const float*)d_in[6];   const float* bv = (const float*)d_in[7];
    const float* Wo = (const float*)d_in[8];   const float* bo = (const float*)d_in[9];
    const float* grep_w = (const float*)d_in[10];
    const float* grep_b = (const float*)d_in[11];
    const float* grep_a = (const float*)d_in[12];
    const float* ln1_g  = (const float*)d_in[13];
    const float* ln1_b  = (const float*)d_in[14];
    const float* W1 = (const float*)d_in[15];  const float* b1 = (const float*)d_in[16];
    const float* W2 = (const float*)d_in[17];  const float* b2 = (const float*)d_in[18];
    const float* ln2_g  = (const float*)d_in[19];
    const float* ln2_b  = (const float*)d_in[20];
    float* out = (float*)d_out;

    __half *hstates, *hWq, *hWk, *hWv, *hWo, *hW1, *hW2;
    __half *hq, *hk, *hv, *hctx, *hx, *hh;
    float  *gate, *y1, *x, *y2;
    cudaGetSymbolAddress((void**)&hstates, g_hstates);
    cudaGetSymbolAddress((void**)&hWq, g_hWq);
    cudaGetSymbolAddress((void**)&hWk, g_hWk);
    cudaGetSymbolAddress((void**)&hWv, g_hWv);
    cudaGetSymbolAddress((void**)&hWo, g_hWo);
    cudaGetSymbolAddress((void**)&hW1, g_hW1);
    cudaGetSymbolAddress((void**)&hW2, g_hW2);
    cudaGetSymbolAddress((void**)&hq,  g_hq);
    cudaGetSymbolAddress((void**)&hk,  g_hk);
    cudaGetSymbolAddress((void**)&hv,  g_hv);
    cudaGetSymbolAddress((void**)&hctx, g_hctx);
    cudaGetSymbolAddress((void**)&hx,  g_hx);
    cudaGetSymbolAddress((void**)&hh,  g_hh);
    cudaGetSymbolAddress((void**)&gate, g_gate);
    cudaGetSymbolAddress((void**)&y1,  g_y1);
    cudaGetSymbolAddress((void**)&x,   g_x);
    cudaGetSymbolAddress((void**)&y2,  g_y2);

    cudaFuncSetAttribute(mm_h<E_QKV>,      cudaFuncAttributeMaxDynamicSharedMemorySize, MM_SMEM);
    cudaFuncSetAttribute(mm_h<E_ADD_ALPHA>,cudaFuncAttributeMaxDynamicSharedMemorySize, MM_SMEM);
    cudaFuncSetAttribute(mm_h<E_GELU>,     cudaFuncAttributeMaxDynamicSharedMemorySize, MM_SMEM);
    cudaFuncSetAttribute(flash_attn_h,     cudaFuncAttributeMaxDynamicSharedMemorySize, FA_SMEM);

    const dim3 blk(256);

    // fp32 -> fp16 for states + weights
    f2h_all<<<2496, blk>>>(states, Wq, Wk, Wv, Wo, W1, W2);

    // Fused QKV projections + gate computation (fp16 tensor cores)
    mm_h<E_QKV><<<dim3(18, 32), blk, MM_SMEM>>>(
        hstates, hWq, hWk, hWv, bq, bk, bv, nullptr, hq, hk, hv,
        grep_w, grep_b, grep_a, gate, D_DIM, 0);

    // tensor-core flash attention (+ fused pb passthrough into out)
    flash_attn_h<<<dim3(T_DIM / 128, NHEADS), blk, FA_SMEM>>>(
        hq, hk, hv, pb, gate, hctx, out + (size_t)NROWS * D_DIM);

    // Wo projection + residual (fp32 aux), then LN1 (fp32 + fp16 out)
    mm_h<E_ADD_ALPHA><<<dim3(6, 32), blk, MM_SMEM>>>(
        hctx, hWo, nullptr, nullptr, bo, nullptr, nullptr,
        states, y1, nullptr, nullptr,
        nullptr, nullptr, nullptr, nullptr, D_DIM, D_DIM);
    layernorm_kernel<<<NROWS, blk>>>(y1, ln1_g, ln1_b, x, hx);

    // FFN
    mm_h<E_GELU><<<dim3(24, 32), blk, MM_SMEM>>>(
        hx, hW1, nullptr, nullptr, b1, nullptr, nullptr,
        nullptr, hh, nullptr, nullptr,
        nullptr, nullptr, nullptr, nullptr, D_DIM, FF_DIM);
    mm_h<E_ADD_ALPHA><<<dim3(6, 32), blk, MM_SMEM>>>(
        hh, hW2, nullptr, nullptr, b2, nullptr, nullptr,
        x, y2, nullptr, nullptr,
        nullptr, nullptr, nullptr, nullptr, FF_DIM, D_DIM);
    layernorm_kernel<<<NROWS, blk>>>(y2, ln2_g, ln2_b, out, nullptr);
}

// round 13
// speedup vs baseline: 5.9276x; 1.0752x over previous
#include <cuda_runtime.h>
#include <cuda_fp16.h>
#include <math.h>

// ---------------------------------------------------------------------------
// Problem constants
// ---------------------------------------------------------------------------
#define T_DIM   1024
#define B_DIM   4
#define D_DIM   768
#define H_DIM   12
#define HD_DIM  64
#define FF_DIM  3072
#define NROWS   4096          // T*B
#define NHEADS  48            // B*H
#define ALPHA_C 2.2133638394006434f   // 24^0.25
#define QSCALE  0.00390625f           // 0.125/32

// ---------------------------------------------------------------------------
// Scratch (device globals: allocation-free rule)
// ---------------------------------------------------------------------------
__device__ __half g_hstates[NROWS * D_DIM];
__device__ __half g_hWq[D_DIM * D_DIM];
__device__ __half g_hWk[D_DIM * D_DIM];
__device__ __half g_hWv[D_DIM * D_DIM];
__device__ __half g_hWo[D_DIM * D_DIM];
__device__ __half g_hW1[FF_DIM * D_DIM];
__device__ __half g_hW2[D_DIM * FF_DIM];
__device__ __half g_hq [NHEADS * T_DIM * HD_DIM];
__device__ __half g_hk [NHEADS * T_DIM * HD_DIM];
__device__ __half g_hv [NHEADS * T_DIM * HD_DIM];
__device__ __half g_hctx[NROWS * D_DIM];
__device__ __half g_hx [NROWS * D_DIM];
__device__ __half g_hh [NROWS * FF_DIM];
__device__ float  g_gate[NHEADS * T_DIM];
__device__ float  g_y1 [NROWS * D_DIM];
__device__ float  g_x  [NROWS * D_DIM];
__device__ float  g_y2 [NROWS * D_DIM];

// ---------------------------------------------------------------------------
// PTX helpers
// ---------------------------------------------------------------------------
__device__ __forceinline__ unsigned sm_u32(const void* p) {
    return (unsigned)__cvta_generic_to_shared(p);
}
__device__ __forceinline__ void cp16(void* s, const void* g) {
    asm volatile("cp.async.ca.shared.global [%0], [%1], 16;\n"
                 :: "r"(sm_u32(s)), "l"(g));
}
#define CP_COMMIT() asm volatile("cp.async.commit_group;\n")
#define CP_WAIT(N)  asm volatile("cp.async.wait_group %0;\n" :: "n"(N))

__device__ __forceinline__ void ldsm_x4(unsigned* f, unsigned addr) {
    asm volatile("ldmatrix.sync.aligned.m8n8.x4.shared.b16 {%0,%1,%2,%3}, [%4];"
                 : "=r"(f[0]), "=r"(f[1]), "=r"(f[2]), "=r"(f[3]) : "r"(addr));
}
__device__ __forceinline__ void ldsm_x4_t(unsigned* f, unsigned addr) {
    asm volatile("ldmatrix.sync.aligned.m8n8.x4.trans.shared.b16 {%0,%1,%2,%3}, [%4];"
                 : "=r"(f[0]), "=r"(f[1]), "=r"(f[2]), "=r"(f[3]) : "r"(addr));
}
__device__ __forceinline__ void mma_fp16(float* d, const unsigned* a,
                                         unsigned b0, unsigned b1) {
    asm volatile(
        "mma.sync.aligned.m16n8k16.row.col.f32.f16.f16.f32 "
        "{%0,%1,%2,%3}, {%4,%5,%6,%7}, {%8,%9}, {%0,%1,%2,%3};\n"
        : "+f"(d[0]), "+f"(d[1]), "+f"(d[2]), "+f"(d[3])
        : "r"(a[0]), "r"(a[1]), "r"(a[2]), "r"(a[3]), "r"(b0), "r"(b1));
}

// ---------------------------------------------------------------------------
// fp32 -> fp16 conversion of states + all 6 weight matrices (one launch)
// ---------------------------------------------------------------------------
__global__ void f2h_all(const float* __restrict__ s0, const float* __restrict__ wq,
                        const float* __restrict__ wk, const float* __restrict__ wv,
                        const float* __restrict__ wo, const float* __restrict__ w1,
                        const float* __restrict__ w2)
{
    const int total4 = 2555904;  // 10,223,616 floats / 4
    for (int i = blockIdx.x * blockDim.x + threadIdx.x; i < total4;
         i += gridDim.x * blockDim.x) {
        int f = i * 4;
        const float* src; __half* dst; int off;
        if      (f < 3145728) { src = s0; dst = g_hstates; off = f; }
        else if (f < 3735552) { src = wq; dst = g_hWq; off = f - 3145728; }
        else if (f < 4325376) { src = wk; dst = g_hWk; off = f - 3735552; }
        else if (f < 4915200) { src = wv; dst = g_hWv; off = f - 4325376; }
        else if (f < 5505024) { src = wo; dst = g_hWo; off = f - 4915200; }
        else if (f < 7864320) { src = w1; dst = g_hW1; off = f - 5505024; }
        else                  { src = w2; dst = g_hW2; off = f - 7864320; }
        float4 v = *(const float4*)(src + off);
        half2* d = (half2*)(dst + off);
        d[0] = __floats2half2_rn(v.x, v.y);
        d[1] = __floats2half2_rn(v.z, v.w);
    }
}

// ---------------------------------------------------------------------------
// prefill: out[n][m] = aux[n][m] * ALPHA + bias[m]   (split-K GEMMs RED into it)
// ---------------------------------------------------------------------------
__global__ void prefill_res(const float* __restrict__ aux,
                            const float* __restrict__ bias,
                            float* __restrict__ out)
{
    const int n4 = NROWS * D_DIM / 4;   // 786432
    for (int i = blockIdx.x * blockDim.x + threadIdx.x; i < n4;
         i += gridDim.x * blockDim.x) {
        float4 a = ((const float4*)aux)[i];
        float4 b = ((const float4*)bias)[i % (D_DIM / 4)];
        float4 o;
        o.x = a.x * ALPHA_C + b.x; o.y = a.y * ALPHA_C + b.y;
        o.z = a.z * ALPHA_C + b.z; o.w = a.w * ALPHA_C + b.w;
        ((float4*)out)[i] = o;
    }
}

// ---------------------------------------------------------------------------
// fp16 tensor-core GEMM, BK=32, 4-stage cp.async pipeline (1 barrier / 32-k).
// C = A(N x K) @ W(M x K)^T  (+ fused epilogue)
// Split-K via gridDim.z (E_ATOMIC: partials RED.ADD into prefilled C).
// E_QKV fuses the gating computation from raw Q outputs.
// ---------------------------------------------------------------------------
enum { E_QKV = 0, E_ATOMIC = 1, E_GELU = 2 };

#define SROW32 40        // halves per smem row (32 data + 8 pad)
#define MM_STAGES 4
#define STG32  (128 * SROW32)                       // halves per operand/stage
#define MM_SMEM (2 * MM_STAGES * STG32 * 2 + 512)   // bytes (+ wsum)

template <int EPI>
__global__ __launch_bounds__(256, 2) void mm_h(
    const __half* __restrict__ A,
    const __half* __restrict__ W0, const __half* __restrict__ W1h, const __half* __restrict__ W2h,
    const float* __restrict__ bp0, const float* __restrict__ bp1, const float* __restrict__ bp2,
    void* __restrict__ C0, void* __restrict__ C1, void* __restrict__ C2,
    const float* __restrict__ gw, const float* __restrict__ gbb,
    const float* __restrict__ gai, float* __restrict__ gate_out,
    int K, int ldc)
{
    extern __shared__ __half smh[];
    __half* Asm = smh;
    __half* Bsm = smh + MM_STAGES * STG32;
    float*  wsum = (float*)(smh + 2 * MM_STAGES * STG32);

    int sel = 0, mblk = blockIdx.x;
    const __half* W = W0; const float* bias = bp0; void* C = C0;
    if (EPI == E_QKV) {
        sel  = blockIdx.x / 6;
        mblk = blockIdx.x % 6;
        if (sel == 1) { W = W1h; bias = bp1; C = C1; }
        else if (sel == 2) { W = W2h; bias = bp2; C = C2; }
    }

    const int n0 = blockIdx.y * 128;
    const int m0 = mblk * 128;
    const int tid  = threadIdx.x;
    const int lane = tid & 31;
    const int wid  = tid >> 5;
    const int wr = (wid >> 1) * 32;
    const int wc = (wid & 1)  * 64;
    const int g = lane >> 2;
    const int c = lane & 3;

    const int KK   = K / gridDim.z;           // K per split
    const int koff = blockIdx.z * KK;
    const int NK   = KK >> 5;

    if (EPI == E_QKV && sel == 0 && tid < 128) {
        const int hd = tid & 63, base = (tid >> 6) * 256;
        wsum[tid] = gw[base + hd] + gw[base + 64 + hd]
                  + gw[base + 128 + hd] + gw[base + 192 + hd];
    }

    float acc[2][8][4];
#pragma unroll
    for (int mf = 0; mf < 2; mf++)
#pragma unroll
        for (int nf = 0; nf < 8; nf++)
#pragma unroll
            for (int r = 0; r < 4; r++) acc[mf][nf][r] = 0.f;

    const __half* Ab = A + (size_t)n0 * K + koff;
    const __half* Wb = W + (size_t)m0 * K + koff;

    // loader: 512 16B-chunks per operand per stage; 2 per thread per operand
    const int lr0 = (tid + 0)   >> 2, ls0 = ((tid + 0)   & 3) * 8;
    const int lr1 = (tid + 256) >> 2, ls1 = ((tid + 256) & 3) * 8;

    // prologue: stages 0..2
#pragma unroll
    for (int s = 0; s < 3; s++) {
        cp16(&Asm[s * STG32 + lr0 * SROW32 + ls0], Ab + (size_t)lr0 * K + s * 32 + ls0);
        cp16(&Asm[s * STG32 + lr1 * SROW32 + ls1], Ab + (size_t)lr1 * K + s * 32 + ls1);
        cp16(&Bsm[s * STG32 + lr0 * SROW32 + ls0], Wb + (size_t)lr0 * K + s * 32 + ls0);
        cp16(&Bsm[s * STG32 + lr1 * SROW32 + ls1], Wb + (size_t)lr1 * K + s * 32 + ls1);
        CP_COMMIT();
    }

    const int a_row = wr + (lane & 15);
    const int a_kb  = (lane >> 4) * 8;
    const int b_row = wc + (lane & 7) + ((lane >> 4) & 1) * 8;
    const int b_kb  = ((lane >> 3) & 1) * 8;

    for (int i = 0; i < NK; i++) {
        const int s   = i % MM_STAGES;
        const int rem = NK - i - 1;
        if      (rem >= 2) CP_WAIT(2);
        else if (rem == 1) CP_WAIT(1);
        else               CP_WAIT(0);
        __syncthreads();

        if (i + 3 < NK) {
            const int s2 = (i + 3) % MM_STAGES;
            const int kt = (i + 3) * 32;
            cp16(&Asm[s2 * STG32 + lr0 * SROW32 + ls0], Ab + (size_t)lr0 * K + kt + ls0);
            cp16(&Asm[s2 * STG32 + lr1 * SROW32 + ls1], Ab + (size_t)lr1 * K + kt + ls1);
            cp16(&Bsm[s2 * STG32 + lr0 * SROW32 + ls0], Wb + (size_t)lr0 * K + kt + ls0);
            cp16(&Bsm[s2 * STG32 + lr1 * SROW32 + ls1], Wb + (size_t)lr1 * K + kt + ls1);
            CP_COMMIT();
        }

#pragma unroll
        for (int kh = 0; kh < 2; kh++) {
            unsigned af[2][4], bf[4][4];
            unsigned abase = sm_u32(&Asm[s * STG32 + a_row * SROW32 + kh * 16 + a_kb]);
            ldsm_x4(af[0], abase);
            ldsm_x4(af[1], abase + 16 * SROW32 * 2);
            unsigned bbase = sm_u32(&Bsm[s * STG32 + b_row * SROW32 + kh * 16 + b_kb]);
#pragma unroll
            for (int bi = 0; bi < 4; bi++)
                ldsm_x4(bf[bi], bbase + bi * 16 * SROW32 * 2);

#pragma unroll
            for (int mf = 0; mf < 2; mf++)
#pragma unroll
                for (int nf = 0; nf < 8; nf++) {
                    const int bi = nf >> 1, hi = (nf & 1) * 2;
                    mma_fp16(acc[mf][nf], af[mf], bf[bi][hi], bf[bi][hi + 1]);
                }
        }
    }

    // gate-path per-thread weights
    float was[16], wbs[16], bsum_a = 0.f, bsum_b = 0.f, gah = 0.f;
    if (EPI == E_QKV && sel == 0) {
#pragma unroll
        for (int nf = 0; nf < 8; nf++) {
            const int hd = (wc + nf * 8 + c * 2) & 63;
            was[nf * 2]     = wsum[hd];
            was[nf * 2 + 1] = wsum[hd + 1];
            wbs[nf * 2]     = wsum[64 + hd];
            wbs[nf * 2 + 1] = wsum[64 + hd + 1];
        }
        bsum_a = gbb[0] + gbb[1] + gbb[2] + gbb[3];
        bsum_b = gbb[4] + gbb[5] + gbb[6] + gbb[7];
        gah = gai[(m0 + wc) >> 6];
    }

    // Epilogue
#pragma unroll
    for (int mf = 0; mf < 2; mf++) {
#pragma unroll
        for (int r2 = 0; r2 < 2; r2++) {
            const int n = n0 + wr + mf * 16 + g + r2 * 8;
            float sa = 0.f, sb = 0.f;
#pragma unroll
            for (int nf = 0; nf < 8; nf++) {
                const int m = m0 + wc + nf * 8 + c * 2;
                if (EPI == E_ATOMIC) {
                    atomicAdd(&((float*)C)[(size_t)n * ldc + m],     acc[mf][nf][r2 * 2]);
                    atomicAdd(&((float*)C)[(size_t)n * ldc + m + 1], acc[mf][nf][r2 * 2 + 1]);
                } else {
                    float v0 = acc[mf][nf][r2 * 2]     + bias[m];
                    float v1 = acc[mf][nf][r2 * 2 + 1] + bias[m + 1];
                    if (EPI == E_QKV) {
                        if (sel == 0) {
                            sa += v0 * was[nf * 2] + v1 * was[nf * 2 + 1];
                            sb += v0 * wbs[nf * 2] + v1 * wbs[nf * 2 + 1];
                            v0 *= QSCALE; v1 *= QSCALE;
                        }
                        const int t = n >> 2, b = n & 3, h = m >> 6, hd = m & 63;
                        *(half2*)&((__half*)C)[(((size_t)(b * H_DIM + h) * T_DIM) + t) * HD_DIM + hd] =
                            __floats2half2_rn(v0, v1);
                    } else { // E_GELU (exact) -> fp16
                        float g0 = 0.5f * v0 * (1.f + erff(v0 * 0.70710678118654752f));
                        float g1 = 0.5f * v1 * (1.f + erff(v1 * 0.70710678118654752f));
                        *(half2*)&((__half*)C)[(size_t)n * ldc + m] = __floats2half2_rn(g0, g1);
                    }
                }
            }
            if (EPI == E_QKV && sel == 0) {
                sa += __shfl_xor_sync(0xffffffffu, sa, 1);
                sa += __shfl_xor_sync(0xffffffffu, sa, 2);
                sb += __shfl_xor_sync(0xffffffffu, sb, 1);
                sb += __shfl_xor_sync(0xffffffffu, sb, 2);
                if (c == 0) {
                    float ga = 1.f / (1.f + __expf(-(sa + bsum_a)));
                    float gb = 1.f / (1.f + __expf(-(sb + bsum_b)));
                    const int t = n >> 2, b = n & 3, h = (m0 + wc) >> 6;
                    gate_out[(b * H_DIM + h) * T_DIM + t] = ga * (gb * gah - 1.f) + 2.f;
                }
            }
        }
    }
}

// ---------------------------------------------------------------------------
// Tensor-core flash attention + fused pb passthrough copy.
// Grid (8, 48): 128 q-rows/CTA, 8 warps x 16 rows.
// 3-stage KV ring -> ONE block barrier per tile; pb staged per-warp.
// smem: Q 128x72h | K 3x64x72h | V 3x64x72h | PB 128x72f | gates 128f
// ---------------------------------------------------------------------------
#define FA_QH   (128 * 72)     // halves
#define FA_KVH  (64 * 72)      // halves per stage
#define FA_SMEM (FA_QH * 2 + 6 * FA_KVH * 2 + 128 * 72 * 4 + 512)

__global__ __launch_bounds__(256, 2) void flash_attn_h(
    const __half* __restrict__ q, const __half* __restrict__ k,
    const __half* __restrict__ v, const float* __restrict__ pb,
    const float* __restrict__ gate, __half* __restrict__ ctx,
    float* __restrict__ outpb)
{
    extern __shared__ __half smh[];
    __half* Qs  = smh;                        // 128x72 h
    __half* Ks  = smh + FA_QH;                // 3 stages 64x72 h
    __half* Vs  = smh + FA_QH + 3 * FA_KVH;   // 3 stages
    float*  PBs = (float*)(smh + FA_QH + 6 * FA_KVH);   // 128x72 f
    float*  Gs  = PBs + 128 * 72;

    const int bh   = blockIdx.y;
    const int q0   = blockIdx.x * 128;
    const int tid  = threadIdx.x;
    const int lane = tid & 31;
    const int w    = tid >> 5;
    const int g    = lane >> 2;
    const int c    = lane & 3;

    const __half* qg = q + ((size_t)bh * T_DIM + q0) * 64;
    const __half* kg = k + (size_t)bh * 65536;
    const __half* vg = v + (size_t)bh * 65536;
    const float*  pbg = pb + ((size_t)bh * T_DIM + q0) * T_DIM;

    // group 1: Q + KV tile0 (stage 0) + pb tile0 ; group 2: KV tile1 (stage 1)
#pragma unroll
    for (int i = tid; i < 1024; i += 256) {
        int row = i >> 3, ch = (i & 7) * 8;
        cp16(&Qs[row * 72 + ch], qg + row * 64 + ch);
    }
#pragma unroll
    for (int i = tid; i < 512; i += 256) {
        int row = i >> 3, ch = (i & 7) * 8;
        cp16(&Ks[row * 72 + ch], kg + row * 64 + ch);
        cp16(&Vs[row * 72 + ch], vg + row * 64 + ch);
    }
#pragma unroll
    for (int it = 0; it < 8; it++) {
        int cidx = lane + it * 32;
        int row  = w * 16 + (cidx >> 4);
        int chf  = (cidx & 15) * 4;
        cp16(&PBs[row * 72 + chf], pbg + (size_t)row * T_DIM + chf);
    }
    CP_COMMIT();
#pragma unroll
    for (int i = tid; i < 512; i += 256) {
        int row = i >> 3, ch = (i & 7) * 8;
        cp16(&Ks[FA_KVH + row * 72 + ch], kg + 4096 + row * 64 + ch);
        cp16(&Vs[FA_KVH + row * 72 + ch], vg + 4096 + row * 64 + ch);
    }
    CP_COMMIT();
    if (tid < 128) Gs[tid] = gate[bh * T_DIM + q0 + tid];

    CP_WAIT(1);
    __syncthreads();

    // Q fragments (persist in registers)
    unsigned af[4][4];
    {
        const int ar  = w * 16 + (lane & 15);
        const int akb = (lane >> 4) * 8;
#pragma unroll
        for (int ks = 0; ks < 4; ks++)
            ldsm_x4(af[ks], sm_u32(&Qs[ar * 72 + ks * 16 + akb]));
    }

    float m0 = -1e30f, m1 = -1e30f, l0 = 0.f, l1 = 0.f;
    float oacc[8][4];
#pragma unroll
    for (int hb = 0; hb < 8; hb++)
#pragma unroll
        for (int j = 0; j < 4; j++) oacc[hb][j] = 0.f;

    const float gr0 = Gs[w * 16 + g];
    const float gr1 = Gs[w * 16 + g + 8];
    float* opb0 = outpb + ((size_t)bh * T_DIM + q0 + w * 16 + g) * T_DIM;
    float* opb1 = opb0 + 8 * T_DIM;

    const int brow = (lane & 7) + ((lane >> 4) & 1) * 8;
    const int bkb  = ((lane >> 3) & 1) * 8;
    const int vr   = lane & 15;
    const int vcb  = (lane >> 4) * 8;
    const int prow0 = (w * 16 + g) * 72;

    for (int t = 0; t < 16; t++) {
        const int st = t % 3;
        // (1) KV(t) ready. outstanding allowed: {PB(t), KV(t+1)}  [t=15: {PB15}]
        if (t) {
            if (t < 15) CP_WAIT(2); else CP_WAIT(1);
            __syncthreads();
        }
        // (1b) early prefetch KV(t+2) into stage (t+2)%3 (freed by barrier above)
        if (t + 2 < 16) {
            const __half* ks2 = kg + (t + 2) * 4096;
            const __half* vs2 = vg + (t + 2) * 4096;
            __half* kd = Ks + ((t + 2) % 3) * FA_KVH;
            __half* vd = Vs + ((t + 2) % 3) * FA_KVH;
#pragma unroll
            for (int i = tid; i < 512; i += 256) {
                int row = i >> 3, ch = (i & 7) * 8;
                cp16(&kd[row * 72 + ch], ks2 + row * 64 + ch);
                cp16(&vd[row * 72 + ch], vs2 + row * 64 + ch);
            }
            CP_COMMIT();
        }
        const __half* Kb = Ks + st * FA_KVH;
        const __half* Vb = Vs + st * FA_KVH;

        // (2) S = Q @ K^T
        float sacc[8][4];
#pragma unroll
        for (int nb = 0; nb < 8; nb++)
#pragma unroll
            for (int j = 0; j < 4; j++) sacc[nb][j] = 0.f;

#pragma unroll
        for (int nb2 = 0; nb2 < 4; nb2++) {
#pragma unroll
            for (int ks = 0; ks < 4; ks++) {
                unsigned bf[4];
                ldsm_x4(bf, sm_u32(&Kb[(nb2 * 16 + brow) * 72 + ks * 16 + bkb]));
                mma_fp16(sacc[nb2 * 2],     af[ks], bf[0], bf[1]);
                mma_fp16(sacc[nb2 * 2 + 1], af[ks], bf[2], bf[3]);
            }
        }

        // (3) PB(t) ready (warp-local rows).
        if (t < 14) CP_WAIT(1); else CP_WAIT(0);
        __syncwarp();

        // (4) logits + passthrough + online softmax
        float mx0 = -1e30f, mx1 = -1e30f;
#pragma unroll
        for (int nb = 0; nb < 8; nb++) {
            float2 p0 = *(const float2*)&PBs[prow0 + nb * 8 + c * 2];
            float2 p1 = *(const float2*)&PBs[prow0 + 8 * 72 + nb * 8 + c * 2];
            *(float2*)&opb0[t * 64 + nb * 8 + c * 2] = p0;
            *(float2*)&opb1[t * 64 + nb * 8 + c * 2] = p1;
            sacc[nb][0] = 32.f * sacc[nb][0] + gr0 * p0.x;
            sacc[nb][1] = 32.f * sacc[nb][1] + gr0 * p0.y;
            sacc[nb][2] = 32.f * sacc[nb][2] + gr1 * p1.x;
            sacc[nb][3] = 32.f * sacc[nb][3] + gr1 * p1.y;
            mx0 = fmaxf(mx0, fmaxf(sacc[nb][0], sacc[nb][1]));
            mx1 = fmaxf(mx1, fmaxf(sacc[nb][2], sacc[nb][3]));
        }
        mx0 = fmaxf(mx0, __shfl_xor_sync(0xffffffffu, mx0, 1));
        mx0 = fmaxf(mx0, __shfl_xor_sync(0xffffffffu, mx0, 2));
        mx1 = fmaxf(mx1, __shfl_xor_sync(0xffffffffu, mx1, 1));
        mx1 = fmaxf(mx1, __shfl_xor_sync(0xffffffffu, mx1, 2));

        const float nm0 = fmaxf(m0, mx0), nm1 = fmaxf(m1, mx1);
        const float corr0 = __expf(m0 - nm0), corr1 = __expf(m1 - nm1);
        m0 = nm0; m1 = nm1;

        unsigned pa[4][4];
        float s0 = 0.f, s1 = 0.f;
#pragma unroll
        for (int nb = 0; nb < 8; nb++) {
            float e0 = __expf(sacc[nb][0] - nm0);
            float e1 = __expf(sacc[nb][1] - nm0);
            float e2 = __expf(sacc[nb][2] - nm1);
            float e3 = __expf(sacc[nb][3] - nm1);
            s0 += e0 + e1; s1 += e2 + e3;
            const int kp = nb >> 1, off = (nb & 1) * 2;
            half2 h0 = __floats2half2_rn(e0, e1);
            half2 h1 = __floats2half2_rn(e2, e3);
            pa[kp][off]     = *(unsigned*)&h0;
            pa[kp][off + 1] = *(unsigned*)&h1;
        }
        s0 += __shfl_xor_sync(0xffffffffu, s0, 1);
        s0 += __shfl_xor_sync(0xffffffffu, s0, 2);
        s1 += __shfl_xor_sync(0xffffffffu, s1, 1);
        s1 += __shfl_xor_sync(0xffffffffu, s1, 2);
        l0 = l0 * corr0 + s0;
        l1 = l1 * corr1 + s1;

#pragma unroll
        for (int hb = 0; hb < 8; hb++) {
            oacc[hb][0] *= corr0; oacc[hb][1] *= corr0;
            oacc[hb][2] *= corr1; oacc[hb][3] *= corr1;
        }

        // (5) warp done reading its PB rows -> warp-local prefetch of pb(t+1)
        __syncwarp();
        if (t + 1 < 16) {
#pragma unroll
            for (int it = 0; it < 8; it++) {
                int cidx = lane + it * 32;
                int row  = w * 16 + (cidx >> 4);
                int chf  = (cidx & 15) * 4;
                cp16(&PBs[row * 72 + chf],
                     pbg + (size_t)row * T_DIM + (t + 1) * 64 + chf);
            }
            CP_COMMIT();
        }

        // (6) out += P @ V   (V loaded transposed); no bottom barrier needed
#pragma unroll
        for (int kp = 0; kp < 4; kp++) {
#pragma unroll
            for (int hb2 = 0; hb2 < 4; hb2++) {
                unsigned bv[4];
                ldsm_x4_t(bv, sm_u32(&Vb[(kp * 16 + vr) * 72 + hb2 * 16 + vcb]));
                mma_fp16(oacc[hb2 * 2],     pa[kp], bv[0], bv[1]);
                mma_fp16(oacc[hb2 * 2 + 1], pa[kp], bv[2], bv[3]);
            }
        }
    }

    // write ctx (fp16, (T,B,D) layout) for Wo GEMM
    const float i0 = 1.f / l0, i1 = 1.f / l1;
    const int b = bh / H_DIM, hh = bh % H_DIM;
    const int t0g = q0 + w * 16 + g;
#pragma unroll
    for (int hb = 0; hb < 8; hb++) {
        const int col = hh * 64 + hb * 8 + c * 2;
        half2 o0 = __floats2half2_rn(oacc[hb][0] * i0, oacc[hb][1] * i0);
        half2 o1 = __floats2half2_rn(oacc[hb][2] * i1, oacc[hb][3] * i1);
        *(half2*)&ctx[(size_t)(t0g * B_DIM + b) * D_DIM + col]       = o0;
        *(half2*)&ctx[(size_t)((t0g + 8) * B_DIM + b) * D_DIM + col] = o1;
    }
}

// ---------------------------------------------------------------------------
// LayerNorm (optionally also emits fp16)
// ---------------------------------------------------------------------------
__global__ void layernorm_kernel(const float* __restrict__ in,
                                 const float* __restrict__ g,
                                 const float* __restrict__ b,
                                 float* __restrict__ out,
                                 __half* __restrict__ hout)
{
    const int row = blockIdx.x, tid = threadIdx.x;
    const float* xr = in + (size_t)row * D_DIM;
    float v0 = xr[tid], v1 = xr[tid + 256], v2 = xr[tid + 512];
    float s  = v0 + v1 + v2;
    float sq = v0 * v0 + v1 * v1 + v2 * v2;
#pragma unroll
    for (int o = 16; o; o >>= 1) {
        s  += __shfl_xor_sync(0xffffffffu, s,  o);
        sq += __shfl_xor_sync(0xffffffffu, sq, o);
    }
    __shared__ float ss[8], sqs[8], stats[2];
    const int w = tid >> 5, lane = tid & 31;
    if (lane == 0) { ss[w] = s; sqs[w] = sq; }
    __syncthreads();
    if (tid == 0) {
        float S = 0.f, SQ = 0.f;
        for (int i = 0; i < 8; i++) { S += ss[i]; SQ += sqs[i]; }
        float mu  = S * (1.f / 768.f);
        float var = SQ * (1.f / 768.f) - mu * mu;
        stats[0] = mu;
        stats[1] = rsqrtf(var + 1e-5f);
    }
    __syncthreads();
    const float mu = stats[0], rstd = stats[1];
    float r0 = (v0 - mu) * rstd * g[tid]       + b[tid];
    float r1 = (v1 - mu) * rstd * g[tid + 256] + b[tid + 256];
    float r2 = (v2 - mu) * rstd * g[tid + 512] + b[tid + 512];
    float* orow = out + (size_t)row * D_DIM;
    orow[tid] = r0; orow[tid + 256] = r1; orow[tid + 512] = r2;
    if (hout) {
        __half* hrow = hout + (size_t)row * D_DIM;
        hrow[tid] = __float2half_rn(r0);
        hrow[tid + 256] = __float2half_rn(r1);
        hrow[tid + 512] = __float2half_rn(r2);
    }
}

// ---------------------------------------------------------------------------
// Launch
// ---------------------------------------------------------------------------
extern "C" void kernel_launch(void* const* d_in, const int* in_sizes, int n_in,
                              void* d_out, int out_size)
{
    const float* states = (const float*)d_in[0];
    const float* pb     = (const float*)d_in[1];
    const float* Wq = (const float*)d_in[2];   const float* bq = (const float*)d_in[3];
    const float* Wk = (const float*)d_in[4];   const float* bk = (const float*)d_in[5];
    const float* Wv = (const float*)d_in[6];   const float* bv = (const float*)d_in[7];
    const float* Wo = (const float*)d_in[8];   const float* bo = (const float*)d_in[9];
    const float* grep_w = (const float*)d_in[10];
    const float* grep_b = (const float*)d_in[11];
    const float* grep_a = (const float*)d_in[12];
    const float* ln1_g  = (const float*)d_in[13];
    const float* ln1_b  = (const float*)d_in[14];
    const float* W1 = (const float*)d_in[15];  const float* b1 = (const float*)d_in[16];
    const float* W2 = (const float*)d_in[17];  const float* b2 = (const float*)d_in[18];
    const float* ln2_g  = (const float*)d_in[19];
    const float* ln2_b  = (const float*)d_in[20];
    float* out = (float*)d_out;

    __half *hstates, *hWq, *hWk, *hWv, *hWo, *hW1, *hW2;
    __half *hq, *hk, *hv, *hctx, *hx, *hh;
    float  *gate, *y1, *x, *y2;
    cudaGetSymbolAddress((void**)&hstates, g_hstates);
    cudaGetSymbolAddress((void**)&hWq, g_hWq);
    cudaGetSymbolAddress((void**)&hWk, g_hWk);
    cudaGetSymbolAddress((void**)&hWv, g_hWv);
    cudaGetSymbolAddress((void**)&hWo, g_hWo);
    cudaGetSymbolAddress((void**)&hW1, g_hW1);
    cudaGetSymbolAddress((void**)&hW2, g_hW2);
    cudaGetSymbolAddress((void**)&hq,  g_hq);
    cudaGetSymbolAddress((void**)&hk,  g_hk);
    cudaGetSymbolAddress((void**)&hv,  g_hv);
    cudaGetSymbolAddress((void**)&hctx, g_hctx);
    cudaGetSymbolAddress((void**)&hx,  g_hx);
    cudaGetSymbolAddress((void**)&hh,  g_hh);
    cudaGetSymbolAddress((void**)&gate, g_gate);
    cudaGetSymbolAddress((void**)&y1,  g_y1);
    cudaGetSymbolAddress((void**)&x,   g_x);
    cudaGetSymbolAddress((void**)&y2,  g_y2);

    cudaFuncSetAttribute(mm_h<E_QKV>,    cudaFuncAttributeMaxDynamicSharedMemorySize, MM_SMEM);
    cudaFuncSetAttribute(mm_h<E_ATOMIC>, cudaFuncAttributeMaxDynamicSharedMemorySize, MM_SMEM);
    cudaFuncSetAttribute(mm_h<E_GELU>,   cudaFuncAttributeMaxDynamicSharedMemorySize, MM_SMEM);
    cudaFuncSetAttribute(flash_attn_h,   cudaFuncAttributeMaxDynamicSharedMemorySize, FA_SMEM);

    const dim3 blk(256);

    // fp32 -> fp16 for states + weights
    f2h_all<<<2496, blk>>>(states, Wq, Wk, Wv, Wo, W1, W2);

    // Fused QKV projections + gate computation (fp16 tensor cores)
    mm_h<E_QKV><<<dim3(18, 32, 1), blk, MM_SMEM>>>(
        hstates, hWq, hWk, hWv, bq, bk, bv, hq, hk, hv,
        grep_w, grep_b, grep_a, gate, D_DIM, 0);

    // tensor-core flash attention (+ fused pb passthrough into out)
    flash_attn_h<<<dim3(T_DIM / 128, NHEADS), blk, FA_SMEM>>>(
        hq, hk, hv, pb, gate, hctx, out + (size_t)NROWS * D_DIM);

    // Wo projection: prefill residual, split-K2 atomic GEMM, LN1
    prefill_res<<<3072, blk>>>(states, bo, y1);
    mm_h<E_ATOMIC><<<dim3(6, 32, 2), blk, MM_SMEM>>>(
        hctx, hWo, nullptr, nullptr, nullptr, nullptr, nullptr,
        y1, nullptr, nullptr,
        nullptr, nullptr, nullptr, nullptr, D_DIM, D_DIM);
    layernorm_kernel<<<NROWS, blk>>>(y1, ln1_g, ln1_b, x, hx);

    // FFN
    mm_h<E_GELU><<<dim3(24, 32, 1), blk, MM_SMEM>>>(
        hx, hW1, nullptr, nullptr, b1, nullptr, nullptr,
        hh, nullptr, nullptr,
        nullptr, nullptr, nullptr, nullptr, D_DIM, FF_DIM);
    prefill_res<<<3072, blk>>>(x, b2, y2);
    mm_h<E_ATOMIC><<<dim3(6, 32, 2), blk, MM_SMEM>>>(
        hh, hW2, nullptr, nullptr, nullptr, nullptr, nullptr,
        y2, nullptr, nullptr,
        nullptr, nullptr, nullptr, nullptr, FF_DIM, D_DIM);
    layernorm_kernel<<<NROWS, blk>>>(y2, ln2_g, ln2_b, out, nullptr);
}